// round 1
// baseline (speedup 1.0000x reference)
#include <cuda_runtime.h>

// ---------------------------------------------------------------------------
// CNNInteractLayer — factored implementation.
// conv(concat(s_i, q_j)) = conv_s(s_i) + conv_q(q_j) + bias   (conv is linear)
// So: compute per-row conv halves once (200 rows), then pairwise add+relu+max.
// ---------------------------------------------------------------------------

#define LSEQ 31
#define DIM 512
#define NROWS 100          // B * N*K = 4 * 25
#define NCC 600            // 4 convs * 150 channels
#define LP 32              // padded L for scratch (float4 friendly)
#define XSTRIDE 37         // odd stride: conflict-free smem transpose
#define HALF_W 1075200     // sum_k k*512*150 = 14 * 76800

// Scratch (device globals: no runtime allocation allowed)
__device__ float g_wT[2 * HALF_W];                 // [half][conv][t][d][c]
__device__ float g_bias[NCC];
__device__ float g_A[NROWS * NCC * LP];            // s-path conv results
__device__ float g_B[NROWS * NCC * LP];            // q-path conv results

// ---------------------------------------------------------------------------
// prep: transpose weights into wT[half][conv][t][d][c] (c contiguous) + bias
// w_k layout: (150, 1024, k)  ->  w[(c*1024 + cin)*k + t]
// ---------------------------------------------------------------------------
__global__ void prep_kernel(const float* __restrict__ w2, const float* __restrict__ b2,
                            const float* __restrict__ w3, const float* __restrict__ b3,
                            const float* __restrict__ w4, const float* __restrict__ b4,
                            const float* __restrict__ w5, const float* __restrict__ b5) {
    int idx = blockIdx.x * blockDim.x + threadIdx.x;
    if (idx < NCC) {
        int conv = idx / 150, c = idx - conv * 150;
        const float* bp = (conv == 0) ? b2 : (conv == 1) ? b3 : (conv == 2) ? b4 : b5;
        g_bias[idx] = bp[c];
    }
    const float* wsrc[4] = {w2, w3, w4, w5};
    const int base[4] = {0, 153600, 384000, 691200};
#pragma unroll
    for (int conv = 0; conv < 4; conv++) {
        int k = conv + 2;
        int n = 2 * k * DIM * 150;
        if (idx < n) {
            int per_half = k * DIM * 150;
            int h = idx / per_half;
            int rem = idx - h * per_half;
            int t = rem / (DIM * 150);
            int rem2 = rem - t * (DIM * 150);
            int d = rem2 / 150;
            int c = rem2 - d * 150;
            g_wT[h * HALF_W + base[conv] + (t * DIM + d) * 150 + c]
                = wsrc[conv][(c * 1024 + h * DIM + d) * k + t];
        }
    }
}

// ---------------------------------------------------------------------------
// conv: one block per (row, conv). Input row transposed into smem, weights
// staged in 32-d chunks, each thread computes a 5cc x 4l register tile.
// y[c,l] = sum_t sum_d w[c,d,t] * x[l + t - pad, d]   (x zero-padded in l)
// Output layout: [row][cc][LP] with l=31 slot set to -1e30 (max-pool pad).
// ---------------------------------------------------------------------------
__global__ void __launch_bounds__(256, 2) conv_kernel(const float* __restrict__ s,
                                                      const float* __restrict__ q) {
    extern __shared__ float smem[];
    float* xs = smem;                       // [DIM][XSTRIDE]
    float* ws = smem + DIM * XSTRIDE;       // [32][160]

    int tid = threadIdx.x;
    int row = blockIdx.x;                   // 0..199
    int conv = blockIdx.y;                  // 0..3
    int h = (row >= NROWS) ? 1 : 0;
    int r = row - h * NROWS;
    const float* x = (h ? q : s) + (size_t)r * (LSEQ * DIM);

    // zero xs (covers l-padding), zero ws pad columns (c 150..159)
    for (int i = tid; i < DIM * XSTRIDE; i += 256) xs[i] = 0.f;
    for (int i = tid; i < 32 * 160; i += 256) ws[i] = 0.f;
    __syncthreads();
    // transposed load: xs[d][l+2] = x[l][d]
    for (int i = tid; i < LSEQ * DIM; i += 256) {
        int l = i / DIM, d = i - l * DIM;
        xs[d * XSTRIDE + l + 2] = x[i];
    }

    int k = conv + 2;
    int pad = (conv >= 2) ? 2 : 1;
    int base = (conv == 0) ? 0 : (conv == 1) ? 153600 : (conv == 2) ? 384000 : 691200;
    const float* wbase = g_wT + h * HALF_W + base;

    int ct = tid >> 3;      // 0..31  -> channels c0..c0+4
    int lt = tid & 7;       // 0..7   -> l positions l0..l0+3
    int c0 = ct * 5;
    int l0 = lt * 4;

    float acc[5][4];
#pragma unroll
    for (int j = 0; j < 5; j++)
#pragma unroll
        for (int i = 0; i < 4; i++) acc[j][i] = 0.f;

    for (int t = 0; t < k; t++) {
        const float* wtap = wbase + t * (DIM * 150);
        int off = t - pad + 2;              // xs l-index offset (>=0)
        for (int dbase = 0; dbase < DIM; dbase += 32) {
            __syncthreads();
            for (int i = tid; i < 32 * 150; i += 256) {
                int dd = i / 150, c = i - dd * 150;
                ws[dd * 160 + c] = wtap[dbase * 150 + i];
            }
            __syncthreads();
#pragma unroll 4
            for (int dd = 0; dd < 32; dd++) {
                const float* xr = &xs[(dbase + dd) * XSTRIDE + l0 + off];
                float xv[4];
#pragma unroll
                for (int i = 0; i < 4; i++) xv[i] = xr[i];
                const float* wr = &ws[dd * 160 + c0];
#pragma unroll
                for (int j = 0; j < 5; j++) {
                    float wv = wr[j];
#pragma unroll
                    for (int i = 0; i < 4; i++)
                        acc[j][i] = fmaf(wv, xv[i], acc[j][i]);
                }
            }
        }
    }

    float* out = (h ? g_B : g_A) + (size_t)r * NCC * LP + conv * 150 * LP;
#pragma unroll
    for (int j = 0; j < 5; j++) {
        int c = c0 + j;
        if (c < 150) {
#pragma unroll
            for (int i = 0; i < 4; i++) {
                int l = l0 + i;
                out[c * LP + l] = (l < LSEQ) ? acc[j][i] : -1e30f;
            }
        }
    }
}

// ---------------------------------------------------------------------------
// combine: one block per pair (b,i,j). out_ch = max(0, max_l(A+B) + bias).
// s_out uses conv channels 0..74, q_out uses 75..149 of each conv.
// ---------------------------------------------------------------------------
__global__ void combine_kernel(float* __restrict__ out) {
    int p = blockIdx.x;                     // 0..2499
    int b = p / 625;
    int rem = p - b * 625;
    int i = rem / 25;
    int j = rem - i * 25;
    const float4* Ap = (const float4*)(g_A + (size_t)(b * 25 + i) * NCC * LP);
    const float4* Bp = (const float4*)(g_B + (size_t)(b * 25 + j) * NCC * LP);

    for (int cc = threadIdx.x; cc < NCC; cc += blockDim.x) {
        float m = -3.0e38f;
#pragma unroll
        for (int l4 = 0; l4 < 8; l4++) {
            float4 a = Ap[cc * 8 + l4];
            float4 bb = Bp[cc * 8 + l4];
            m = fmaxf(m, a.x + bb.x);
            m = fmaxf(m, a.y + bb.y);
            m = fmaxf(m, a.z + bb.z);
            m = fmaxf(m, a.w + bb.w);
        }
        m = fmaxf(0.f, m + g_bias[cc]);
        int conv = cc / 150;
        int c = cc - conv * 150;
        if (c < 75)
            out[p * 300 + conv * 75 + c] = m;                   // s_out
        else
            out[750000 + p * 300 + conv * 75 + (c - 75)] = m;   // q_out
    }
}

// ---------------------------------------------------------------------------
extern "C" void kernel_launch(void* const* d_in, const int* in_sizes, int n_in,
                              void* d_out, int out_size) {
    const float* s  = (const float*)d_in[0];
    const float* q  = (const float*)d_in[1];
    const float* w2 = (const float*)d_in[2];
    const float* b2 = (const float*)d_in[3];
    const float* w3 = (const float*)d_in[4];
    const float* b3 = (const float*)d_in[5];
    const float* w4 = (const float*)d_in[6];
    const float* b4 = (const float*)d_in[7];
    const float* w5 = (const float*)d_in[8];
    const float* b5 = (const float*)d_in[9];
    float* out = (float*)d_out;

    const int smem_bytes = (DIM * XSTRIDE + 32 * 160) * sizeof(float);  // 96256
    cudaFuncSetAttribute(conv_kernel, cudaFuncAttributeMaxDynamicSharedMemorySize,
                         smem_bytes);

    // 2*5*512*150 = 768000 elements max -> 3000 blocks of 256
    prep_kernel<<<3000, 256>>>(w2, b2, w3, b3, w4, b4, w5, b5);
    dim3 cgrid(200, 4);
    conv_kernel<<<cgrid, 256, smem_bytes>>>(s, q);
    combine_kernel<<<2500, 256>>>(out);
}

// round 2
// speedup vs baseline: 1.1632x; 1.1632x over previous
#include <cuda_runtime.h>

// ---------------------------------------------------------------------------
// CNNInteractLayer — factored implementation.
// conv(concat(s_i, q_j)) = conv_s(s_i) + conv_q(q_j) + bias   (conv is linear)
// Compute per-row conv halves once (200 rows), then pairwise add+relu+max.
// Conv inner loop uses Blackwell packed fma.rn.f32x2 (2 fp32 FMA / instr).
// ---------------------------------------------------------------------------

#define LSEQ 31
#define DIM 512
#define NROWS 100          // B * N*K = 4 * 25
#define NCC 600            // 4 convs * 150 channels
#define LP 32              // padded L for scratch (float4 friendly)
#define XSTRIDE 37         // odd stride: conflict-free smem transpose
#define HALF_W 1075200     // sum_k k*512*150 = 14 * 76800

typedef unsigned long long ull;

__device__ float g_wT[2 * HALF_W];                 // [half][conv][t][d][c]
__device__ float g_bias[NCC];
__device__ float g_A[NROWS * NCC * LP];            // s-path conv results
__device__ float g_B[NROWS * NCC * LP];            // q-path conv results

__device__ __forceinline__ ull fma2(ull a, ull b, ull c) {
    ull d;
    asm("fma.rn.f32x2 %0, %1, %2, %3;" : "=l"(d) : "l"(a), "l"(b), "l"(c));
    return d;
}
__device__ __forceinline__ ull pack2(float lo, float hi) {
    ull d;
    asm("mov.b64 %0, {%1, %2};" : "=l"(d) : "f"(lo), "f"(hi));
    return d;
}
__device__ __forceinline__ void unpack2(ull v, float& lo, float& hi) {
    asm("mov.b64 {%0, %1}, %2;" : "=f"(lo), "=f"(hi) : "l"(v));
}

// ---------------------------------------------------------------------------
// prep: transpose weights into wT[half][conv][t][d][c] (c contiguous) + bias
// w_k layout: (150, 1024, k)  ->  w[(c*1024 + cin)*k + t]
// ---------------------------------------------------------------------------
__global__ void prep_kernel(const float* __restrict__ w2, const float* __restrict__ b2,
                            const float* __restrict__ w3, const float* __restrict__ b3,
                            const float* __restrict__ w4, const float* __restrict__ b4,
                            const float* __restrict__ w5, const float* __restrict__ b5) {
    int idx = blockIdx.x * blockDim.x + threadIdx.x;
    if (idx < NCC) {
        int conv = idx / 150, c = idx - conv * 150;
        const float* bp = (conv == 0) ? b2 : (conv == 1) ? b3 : (conv == 2) ? b4 : b5;
        g_bias[idx] = bp[c];
    }
    const float* wsrc[4] = {w2, w3, w4, w5};
    const int base[4] = {0, 153600, 384000, 691200};
#pragma unroll
    for (int conv = 0; conv < 4; conv++) {
        int k = conv + 2;
        int n = 2 * k * DIM * 150;
        if (idx < n) {
            int per_half = k * DIM * 150;
            int h = idx / per_half;
            int rem = idx - h * per_half;
            int t = rem / (DIM * 150);
            int rem2 = rem - t * (DIM * 150);
            int d = rem2 / 150;
            int c = rem2 - d * 150;
            g_wT[h * HALF_W + base[conv] + (t * DIM + d) * 150 + c]
                = wsrc[conv][(c * 1024 + h * DIM + d) * k + t];
        }
    }
}

// ---------------------------------------------------------------------------
// conv: one block per (row, conv). Input row transposed into smem, weights
// staged in 32-d chunks. Thread tile: 10 channels (5 f32x2 pairs) x 2 l.
// y[c,l] = sum_t sum_d w[c,d,t] * x[l + t - pad, d]   (x zero-padded in l)
// Output layout: [row][cc][LP] with l=31 slot set to -1e30 (max-pool pad).
// ---------------------------------------------------------------------------
__global__ void __launch_bounds__(256, 2) conv_kernel(const float* __restrict__ s,
                                                      const float* __restrict__ q) {
    extern __shared__ float smem[];
    float* xs = smem;                       // [DIM][XSTRIDE]
    float* ws = smem + DIM * XSTRIDE;       // [32][160]

    int tid = threadIdx.x;
    int row = blockIdx.x;                   // 0..199
    int conv = blockIdx.y;                  // 0..3
    int h = (row >= NROWS) ? 1 : 0;
    int r = row - h * NROWS;
    const float* x = (h ? q : s) + (size_t)r * (LSEQ * DIM);

    // zero xs (covers l-padding)
    for (int i = tid; i < DIM * XSTRIDE; i += 256) xs[i] = 0.f;
    __syncthreads();
    // transposed load: xs[d][l+2] = x[l][d]
    for (int i = tid; i < LSEQ * DIM; i += 256) {
        int l = i / DIM, d = i - l * DIM;
        xs[d * XSTRIDE + l + 2] = x[i];
    }

    int k = conv + 2;
    int pad = (conv >= 2) ? 2 : 1;
    int base = (conv == 0) ? 0 : (conv == 1) ? 153600 : (conv == 2) ? 384000 : 691200;
    const float* wbase = g_wT + h * HALF_W + base;

    int ctg = tid >> 4;     // 0..15 (15 active) -> channels c0..c0+9
    int lg = tid & 15;      // 0..15            -> l positions l0, l0+1
    int c0 = ctg * 10;
    int l0 = lg * 2;
    bool active = (ctg < 15);

    ull acc[5][2];
#pragma unroll
    for (int j = 0; j < 5; j++) { acc[j][0] = 0ULL; acc[j][1] = 0ULL; }

    for (int t = 0; t < k; t++) {
        const float* wtap = wbase + t * (DIM * 150);
        int off = t - pad + 2;              // xs l-index offset (>=0)
        for (int dbase = 0; dbase < DIM; dbase += 32) {
            __syncthreads();
            for (int i = tid; i < 32 * 150; i += 256) {
                int dd = i / 150, c = i - dd * 150;
                ws[dd * 160 + c] = wtap[dbase * 150 + i];
            }
            __syncthreads();
            if (active) {
#pragma unroll 4
                for (int dd = 0; dd < 32; dd++) {
                    const float* xr = &xs[(dbase + dd) * XSTRIDE + l0 + off];
                    float x0 = xr[0], x1 = xr[1];
                    ull xp0 = pack2(x0, x0);
                    ull xp1 = pack2(x1, x1);
                    const float* wr = &ws[dd * 160 + c0];
#pragma unroll
                    for (int j = 0; j < 5; j++) {
                        ull wp = *(const ull*)(wr + 2 * j);   // aligned LDS.64
                        acc[j][0] = fma2(wp, xp0, acc[j][0]);
                        acc[j][1] = fma2(wp, xp1, acc[j][1]);
                    }
                }
            }
        }
    }

    if (active) {
        float* out = (h ? g_B : g_A) + (size_t)r * NCC * LP + conv * 150 * LP;
#pragma unroll
        for (int j = 0; j < 5; j++) {
#pragma unroll
            for (int i = 0; i < 2; i++) {
                int l = l0 + i;
                float vlo, vhi;
                unpack2(acc[j][i], vlo, vhi);
                out[(c0 + 2 * j) * LP + l]     = (l < LSEQ) ? vlo : -1e30f;
                out[(c0 + 2 * j + 1) * LP + l] = (l < LSEQ) ? vhi : -1e30f;
            }
        }
    }
}

// ---------------------------------------------------------------------------
// combine: one block per pair (b,i,j). out_ch = max(0, max_l(A+B) + bias).
// s_out uses conv channels 0..74, q_out uses 75..149 of each conv.
// ---------------------------------------------------------------------------
__global__ void combine_kernel(float* __restrict__ out) {
    int p = blockIdx.x;                     // 0..2499
    int b = p / 625;
    int rem = p - b * 625;
    int i = rem / 25;
    int j = rem - i * 25;
    const float4* Ap = (const float4*)(g_A + (size_t)(b * 25 + i) * NCC * LP);
    const float4* Bp = (const float4*)(g_B + (size_t)(b * 25 + j) * NCC * LP);

    for (int cc = threadIdx.x; cc < NCC; cc += blockDim.x) {
        float m = -3.0e38f;
#pragma unroll
        for (int l4 = 0; l4 < 8; l4++) {
            float4 a = Ap[cc * 8 + l4];
            float4 bb = Bp[cc * 8 + l4];
            m = fmaxf(m, a.x + bb.x);
            m = fmaxf(m, a.y + bb.y);
            m = fmaxf(m, a.z + bb.z);
            m = fmaxf(m, a.w + bb.w);
        }
        m = fmaxf(0.f, m + g_bias[cc]);
        int conv = cc / 150;
        int c = cc - conv * 150;
        if (c < 75)
            out[p * 300 + conv * 75 + c] = m;                   // s_out
        else
            out[750000 + p * 300 + conv * 75 + (c - 75)] = m;   // q_out
    }
}

// ---------------------------------------------------------------------------
extern "C" void kernel_launch(void* const* d_in, const int* in_sizes, int n_in,
                              void* d_out, int out_size) {
    const float* s  = (const float*)d_in[0];
    const float* q  = (const float*)d_in[1];
    const float* w2 = (const float*)d_in[2];
    const float* b2 = (const float*)d_in[3];
    const float* w3 = (const float*)d_in[4];
    const float* b3 = (const float*)d_in[5];
    const float* w4 = (const float*)d_in[6];
    const float* b4 = (const float*)d_in[7];
    const float* w5 = (const float*)d_in[8];
    const float* b5 = (const float*)d_in[9];
    float* out = (float*)d_out;

    const int smem_bytes = (DIM * XSTRIDE + 32 * 160) * sizeof(float);  // 96256
    cudaFuncSetAttribute(conv_kernel, cudaFuncAttributeMaxDynamicSharedMemorySize,
                         smem_bytes);

    prep_kernel<<<3000, 256>>>(w2, b2, w3, b3, w4, b4, w5, b5);
    dim3 cgrid(200, 4);
    conv_kernel<<<cgrid, 256, smem_bytes>>>(s, q);
    combine_kernel<<<2500, 256>>>(out);
}

// round 3
// speedup vs baseline: 1.8249x; 1.5690x over previous
#include <cuda_runtime.h>
#include <cstdint>

// ---------------------------------------------------------------------------
// CNNInteractLayer — GEMM-factored implementation.
// conv(concat(s_i,q_j)) = conv_s(s_i) + conv_q(q_j) + bias  (conv is linear).
// Per half: Z[M=2100][N=3200] = W[2100x512] @ X[512x3200], M = (conv,tap,ch),
// N = (row, l-padded-to-32). Then shift-add epilogue builds per-row conv
// halves, then pairwise combine (add + bias + relu + maxpool).
// ---------------------------------------------------------------------------

#define LSEQ 31
#define DIM 512
#define NROWS 100          // rows per half (B * N*K = 4 * 25)
#define NCC 600            // 4 convs * 150 channels
#define LP 32
#define MTOT 2100          // sum_k k*150 = 14*150
#define MSTR 2176          // padded to 17*128
#define NSTR 3200          // 100 rows * 32
#define BM 128
#define BN 128
#define BK 16

typedef unsigned long long ull;

__device__ float g_Wg[2 * DIM * MSTR];             // [half][d][m]  (m padded)
__device__ float g_X[2 * DIM * NSTR];              // [half][d][r*32+l]
__device__ float g_Z[2 * MSTR * NSTR];             // GEMM result
__device__ float g_bias[NCC];
__device__ float g_A[NROWS * NCC * LP];            // s-path conv results
__device__ float g_B[NROWS * NCC * LP];            // q-path conv results

__device__ __forceinline__ ull fma2(ull a, ull b, ull c) {
    ull d;
    asm("fma.rn.f32x2 %0, %1, %2, %3;" : "=l"(d) : "l"(a), "l"(b), "l"(c));
    return d;
}
__device__ __forceinline__ ull pack2(float lo, float hi) {
    ull d;
    asm("mov.b64 %0, {%1, %2};" : "=l"(d) : "f"(lo), "f"(hi));
    return d;
}
__device__ __forceinline__ uint32_t s2u(const void* p) {
    uint32_t a;
    asm("{ .reg .u64 t; cvta.to.shared.u64 t, %1; cvt.u32.u64 %0, t; }"
        : "=r"(a) : "l"(p));
    return a;
}
__device__ __forceinline__ void cp16(uint32_t saddr, const void* gptr) {
    asm volatile("cp.async.cg.shared.global [%0], [%1], 16;"
                 :: "r"(saddr), "l"(gptr));
}
__device__ __forceinline__ void cp_commit() {
    asm volatile("cp.async.commit_group;");
}
__device__ __forceinline__ void cp_wait0() {
    asm volatile("cp.async.wait_group 0;");
}

// ---------------------------------------------------------------------------
// prep: Wg[h][d][m] with m = convbase + t*150 + c (zero-padded to MSTR) + bias
// w_k layout: (150, 1024, k) -> w[(c*1024 + cin)*k + t]
// ---------------------------------------------------------------------------
__global__ void prep_kernel(const float* __restrict__ w2, const float* __restrict__ b2,
                            const float* __restrict__ w3, const float* __restrict__ b3,
                            const float* __restrict__ w4, const float* __restrict__ b4,
                            const float* __restrict__ w5, const float* __restrict__ b5) {
    int idx = blockIdx.x * blockDim.x + threadIdx.x;
    if (idx < NCC) {
        int conv = idx / 150, c = idx - conv * 150;
        const float* bp = (conv == 0) ? b2 : (conv == 1) ? b3 : (conv == 2) ? b4 : b5;
        g_bias[idx] = bp[c];
    }
    if (idx >= 2 * DIM * MSTR) return;
    int h = idx / (DIM * MSTR);
    int rem = idx - h * (DIM * MSTR);
    int d = rem / MSTR;
    int m = rem - d * MSTR;
    float val = 0.f;
    if (m < MTOT) {
        int conv = (m < 300) ? 0 : (m < 750) ? 1 : (m < 1350) ? 2 : 3;
        int base = (conv == 0) ? 0 : (conv == 1) ? 300 : (conv == 2) ? 750 : 1350;
        int k = conv + 2;
        int mm = m - base;
        int t = mm / 150, c = mm - t * 150;
        const float* w = (conv == 0) ? w2 : (conv == 1) ? w3 : (conv == 2) ? w4 : w5;
        val = w[(c * 1024 + h * DIM + d) * k + t];
    }
    g_Wg[idx] = val;
}

// ---------------------------------------------------------------------------
// xbuild: transpose inputs into X[h][d][r*32+l], l=31 slot zeroed.
// ---------------------------------------------------------------------------
__global__ void xbuild_kernel(const float* __restrict__ s, const float* __restrict__ q) {
    extern __shared__ float xs[];           // [512][33]
    int r = blockIdx.x, h = blockIdx.y;
    int tid = threadIdx.x;
    const float* x = (h ? q : s) + (size_t)r * (LSEQ * DIM);
    for (int i = tid; i < LSEQ * DIM; i += 256) {
        int l = i >> 9, d = i & 511;
        xs[d * 33 + l] = x[i];
    }
    __syncthreads();
    float* gx = g_X + (size_t)h * DIM * NSTR + r * 32;
    for (int i = tid; i < DIM * 32; i += 256) {
        int d = i >> 5, l = i & 31;
        gx[(size_t)d * NSTR + l] = (l < LSEQ) ? xs[d * 33 + l] : 0.f;
    }
}

// ---------------------------------------------------------------------------
// gemm: Z[h] = Wg[h]^T-view @ X[h].  128x128x16 tiles, double-buffered
// cp.async staging, f32x2 accumulators (8 m x 4 n-pairs per thread).
// ---------------------------------------------------------------------------
__global__ void __launch_bounds__(256, 2) gemm_kernel() {
    __shared__ float smem[8192];            // As[2][16][128] | Bs[2][16][128]
    int tid = threadIdx.x;
    int bx = blockIdx.x, by = blockIdx.y, h = blockIdx.z;

    const float* Wp = g_Wg + (size_t)h * DIM * MSTR + by * BM;
    const float* Xp = g_X + (size_t)h * DIM * NSTR + bx * BN;

    uint32_t sbase = s2u(smem);
    // staging chunk indices (16B chunks): 512 per tile, 2 per thread per tile
    int kkA0 = tid >> 5, fA0 = (tid & 31) * 4;
    int kkA1 = (tid + 256) >> 5, fA1 = ((tid + 256) & 31) * 4;

    int mg = tid >> 4, lg = tid & 15;
    int m0 = mg * 8, n0 = lg * 8;

    ull acc[8][4];
#pragma unroll
    for (int m = 0; m < 8; m++)
#pragma unroll
        for (int np = 0; np < 4; np++) acc[m][np] = 0ULL;

#define STAGE(kb, buf)                                                          \
    {                                                                           \
        uint32_t aoff = sbase + (buf) * 8192;                                   \
        uint32_t boff = sbase + 16384 + (buf) * 8192;                           \
        cp16(aoff + (kkA0 * BM + fA0) * 4, Wp + (size_t)((kb) * BK + kkA0) * MSTR + fA0); \
        cp16(aoff + (kkA1 * BM + fA1) * 4, Wp + (size_t)((kb) * BK + kkA1) * MSTR + fA1); \
        cp16(boff + (kkA0 * BN + fA0) * 4, Xp + (size_t)((kb) * BK + kkA0) * NSTR + fA0); \
        cp16(boff + (kkA1 * BN + fA1) * 4, Xp + (size_t)((kb) * BK + kkA1) * NSTR + fA1); \
        cp_commit();                                                            \
    }

    STAGE(0, 0);
    cp_wait0();
    __syncthreads();

    int buf = 0;
    for (int kb = 0; kb < DIM / BK; kb++) {
        if (kb + 1 < DIM / BK) STAGE(kb + 1, buf ^ 1);

        const float* As = smem + buf * 2048;
        const float* Bs = smem + 4096 + buf * 2048;
#pragma unroll
        for (int kk = 0; kk < BK; kk++) {
            float4 w0 = *(const float4*)(As + kk * BM + m0);
            float4 w1 = *(const float4*)(As + kk * BM + m0 + 4);
            ulonglong2 xa = *(const ulonglong2*)(Bs + kk * BN + n0);
            ulonglong2 xb = *(const ulonglong2*)(Bs + kk * BN + n0 + 4);
            ull xp[4] = {xa.x, xa.y, xb.x, xb.y};
            float wv[8] = {w0.x, w0.y, w0.z, w0.w, w1.x, w1.y, w1.z, w1.w};
#pragma unroll
            for (int m = 0; m < 8; m++) {
                ull wp = pack2(wv[m], wv[m]);
#pragma unroll
                for (int np = 0; np < 4; np++)
                    acc[m][np] = fma2(xp[np], wp, acc[m][np]);
            }
        }
        if (kb + 1 < DIM / BK) cp_wait0();
        __syncthreads();
        buf ^= 1;
    }
#undef STAGE

    float* Zp = g_Z + (size_t)h * MSTR * NSTR + (size_t)(by * BM) * NSTR + bx * BN;
#pragma unroll
    for (int m = 0; m < 8; m++) {
        float* zr = Zp + (size_t)(m0 + m) * NSTR + n0;
#pragma unroll
        for (int np = 0; np < 4; np++)
            *(ull*)(zr + np * 2) = acc[m][np];
    }
}

// ---------------------------------------------------------------------------
// epilogue: Y[h][r][conv*150+c][l] = sum_t Z[h][(base+t*150+c)][r*32 + l+t-pad]
// l=31 slot set to -1e30 (max-pool pad).
// ---------------------------------------------------------------------------
__global__ void epilogue_kernel() {
    int r = blockIdx.x, conv = blockIdx.y, h = blockIdx.z;
    int k = conv + 2;
    int pad = (conv >= 2) ? 2 : 1;
    int base = (conv == 0) ? 0 : (conv == 1) ? 300 : (conv == 2) ? 750 : 1350;
    const float* Zp = g_Z + (size_t)h * MSTR * NSTR + r * 32;
    float* out = (h ? g_B : g_A) + (size_t)r * NCC * LP + conv * 150 * LP;
    for (int i = threadIdx.x; i < 150 * 32; i += 256) {
        int c = i >> 5, l = i & 31;
        float v = -1e30f;
        if (l < LSEQ) {
            v = 0.f;
            for (int t = 0; t < k; t++) {
                int lp = l + t - pad;
                if (lp >= 0 && lp < 32)
                    v += Zp[(size_t)(base + t * 150 + c) * NSTR + lp];
            }
        }
        out[c * LP + l] = v;
    }
}

// ---------------------------------------------------------------------------
// combine: one block per pair (b,i,j). out_ch = max(0, max_l(A+B) + bias).
// ---------------------------------------------------------------------------
__global__ void combine_kernel(float* __restrict__ out) {
    int p = blockIdx.x;                     // 0..2499
    int b = p / 625;
    int rem = p - b * 625;
    int i = rem / 25;
    int j = rem - i * 25;
    const float4* Ap = (const float4*)(g_A + (size_t)(b * 25 + i) * NCC * LP);
    const float4* Bp = (const float4*)(g_B + (size_t)(b * 25 + j) * NCC * LP);

    for (int cc = threadIdx.x; cc < NCC; cc += blockDim.x) {
        float m = -3.0e38f;
#pragma unroll
        for (int l4 = 0; l4 < 8; l4++) {
            float4 a = Ap[cc * 8 + l4];
            float4 bb = Bp[cc * 8 + l4];
            m = fmaxf(m, a.x + bb.x);
            m = fmaxf(m, a.y + bb.y);
            m = fmaxf(m, a.z + bb.z);
            m = fmaxf(m, a.w + bb.w);
        }
        m = fmaxf(0.f, m + g_bias[cc]);
        int conv = cc / 150;
        int c = cc - conv * 150;
        if (c < 75)
            out[p * 300 + conv * 75 + c] = m;                   // s_out
        else
            out[750000 + p * 300 + conv * 75 + (c - 75)] = m;   // q_out
    }
}

// ---------------------------------------------------------------------------
extern "C" void kernel_launch(void* const* d_in, const int* in_sizes, int n_in,
                              void* d_out, int out_size) {
    const float* s  = (const float*)d_in[0];
    const float* q  = (const float*)d_in[1];
    const float* w2 = (const float*)d_in[2];
    const float* b2 = (const float*)d_in[3];
    const float* w3 = (const float*)d_in[4];
    const float* b3 = (const float*)d_in[5];
    const float* w4 = (const float*)d_in[6];
    const float* b4 = (const float*)d_in[7];
    const float* w5 = (const float*)d_in[8];
    const float* b5 = (const float*)d_in[9];
    float* out = (float*)d_out;

    const int xb_smem = 512 * 33 * sizeof(float);   // 67584
    cudaFuncSetAttribute(xbuild_kernel, cudaFuncAttributeMaxDynamicSharedMemorySize,
                         xb_smem);

    prep_kernel<<<(2 * DIM * MSTR + 255) / 256, 256>>>(w2, b2, w3, b3, w4, b4, w5, b5);
    xbuild_kernel<<<dim3(NROWS, 2), 256, xb_smem>>>(s, q);
    gemm_kernel<<<dim3(NSTR / BN, MSTR / BM, 2), 256>>>();
    epilogue_kernel<<<dim3(NROWS, 4, 2), 256>>>();
    combine_kernel<<<2500, 256>>>(out);
}

// round 5
// speedup vs baseline: 2.7871x; 1.5272x over previous
#include <cuda_runtime.h>
#include <cuda_bf16.h>
#include <cstdint>

// ---------------------------------------------------------------------------
// CNNInteractLayer — mma.sync bf16x3 GEMM-factored implementation.
// conv(concat(s_i,q_j)) = conv_s(s_i) + conv_q(q_j) + bias  (conv is linear).
// Per half: Z[2176x3200] = W[2176x512] @ X[512x3200]^T-view on tensor cores,
// bf16 2-term split stacked along K (K=1536): [Wh,Wl,Wh] . [Xh,Xh,Xl]
// = hi*hi + lo*hi + hi*lo, fp32 accumulation.
// Then shift-add epilogue + pairwise combine (add + bias + relu + maxpool).
// ---------------------------------------------------------------------------

#define LSEQ 31
#define DIM 512
#define NROWS 100
#define NCC 600
#define LP 32
#define MTOT 2100
#define MSTR 2176          // 17 * 128
#define NSTR 3200          // 100 rows * 32 = 25 * 128
#define NCH 24             // (3 * 512) / 64 k-chunks

typedef unsigned long long ull;

__device__ __nv_bfloat16 g_Wh[2 * MSTR * DIM];     // [half][m][k]
__device__ __nv_bfloat16 g_Wl[2 * MSTR * DIM];
__device__ __nv_bfloat16 g_Xh[2 * NSTR * DIM];     // [half][n][k]
__device__ __nv_bfloat16 g_Xl[2 * NSTR * DIM];
__device__ float g_Z[2 * (size_t)MSTR * NSTR];
__device__ float g_bias[NCC];
__device__ float g_A[NROWS * NCC * LP];
__device__ float g_B[NROWS * NCC * LP];

// ---------------- PTX helpers (all plain compute_100-legal) ----------------
__device__ __forceinline__ uint32_t s2u(const void* p) {
    uint32_t a;
    asm("{ .reg .u64 t; cvta.to.shared.u64 t, %1; cvt.u32.u64 %0, t; }"
        : "=r"(a) : "l"(p));
    return a;
}
__device__ __forceinline__ void cp16(uint32_t saddr, const void* gptr) {
    asm volatile("cp.async.cg.shared.global [%0], [%1], 16;"
                 :: "r"(saddr), "l"(gptr));
}
__device__ __forceinline__ void ldsm4(uint32_t* r, uint32_t addr) {
    asm volatile("ldmatrix.sync.aligned.m8n8.x4.shared.b16 {%0,%1,%2,%3}, [%4];"
                 : "=r"(r[0]), "=r"(r[1]), "=r"(r[2]), "=r"(r[3]) : "r"(addr));
}
__device__ __forceinline__ void mma_bf16(float* d, const uint32_t* a,
                                         const uint32_t* b) {
    asm volatile(
        "mma.sync.aligned.m16n8k16.row.col.f32.bf16.bf16.f32 "
        "{%0,%1,%2,%3}, {%4,%5,%6,%7}, {%8,%9}, {%0,%1,%2,%3};"
        : "+f"(d[0]), "+f"(d[1]), "+f"(d[2]), "+f"(d[3])
        : "r"(a[0]), "r"(a[1]), "r"(a[2]), "r"(a[3]), "r"(b[0]), "r"(b[1]));
}
#define SW128(x) ((x) ^ (((x) >> 3) & 0x70))

// ---------------------------------------------------------------------------
// wsplit: gather weights into W[h][m][k], split fp32 -> bf16 hi/lo. + bias
// w_k layout: (150, 1024, k) -> w[(c*1024 + cin)*k + t]; m = base + t*150 + c
// ---------------------------------------------------------------------------
__global__ void wsplit_kernel(const float* __restrict__ w2, const float* __restrict__ b2,
                              const float* __restrict__ w3, const float* __restrict__ b3,
                              const float* __restrict__ w4, const float* __restrict__ b4,
                              const float* __restrict__ w5, const float* __restrict__ b5) {
    int idx = blockIdx.x * blockDim.x + threadIdx.x;
    if (idx < NCC) {
        int conv = idx / 150, c = idx - conv * 150;
        const float* bp = (conv == 0) ? b2 : (conv == 1) ? b3 : (conv == 2) ? b4 : b5;
        g_bias[idx] = bp[c];
    }
    if (idx >= 2 * MSTR * DIM) return;
    int h = idx / (MSTR * DIM);
    int rem = idx - h * (MSTR * DIM);
    int m = rem / DIM;
    int d = rem - m * DIM;
    float v = 0.f;
    if (m < MTOT) {
        int conv = (m < 300) ? 0 : (m < 750) ? 1 : (m < 1350) ? 2 : 3;
        int base = (conv == 0) ? 0 : (conv == 1) ? 300 : (conv == 2) ? 750 : 1350;
        int k = conv + 2;
        int mm = m - base;
        int t = mm / 150, c = mm - t * 150;
        const float* w = (conv == 0) ? w2 : (conv == 1) ? w3 : (conv == 2) ? w4 : w5;
        v = w[(c * 1024 + h * DIM + d) * k + t];
    }
    __nv_bfloat16 hi = __float2bfloat16(v);
    g_Wh[idx] = hi;
    g_Wl[idx] = __float2bfloat16(v - __bfloat162float(hi));
}

// ---------------------------------------------------------------------------
// xsplit: X[h][n=r*32+l][k=d] from inputs (d-contiguous already); l=31 -> 0.
// ---------------------------------------------------------------------------
__global__ void xsplit_kernel(const float* __restrict__ s, const float* __restrict__ q) {
    int idx = blockIdx.x * blockDim.x + threadIdx.x;
    if (idx >= 2 * NSTR * DIM) return;
    int h = idx / (NSTR * DIM);
    int rem = idx - h * (NSTR * DIM);
    int n = rem / DIM;
    int d = rem - n * DIM;
    int r = n >> 5, l = n & 31;
    const float* x = (h ? q : s);
    float v = (l < LSEQ) ? x[((size_t)r * LSEQ + l) * DIM + d] : 0.f;
    __nv_bfloat16 hi = __float2bfloat16(v);
    g_Xh[idx] = hi;
    g_Xl[idx] = __float2bfloat16(v - __bfloat162float(hi));
}

// ---------------------------------------------------------------------------
// gemm: 128x128 block tile, 8 warps (2m x 4n, warp tile 64x32), BK=64,
// double-buffered cp.async, SW128 smem, ldmatrix + mma.sync bf16.
// K iterates over 24 chunks = 3 segments (hi*hi, lo*hi, hi*lo) x 8.
// ---------------------------------------------------------------------------
#define SM_BUF 32768            // per buffer: A 16KB + B 16KB
#define SM_TOTAL 65536

__global__ void __launch_bounds__(256) gemm_kernel() {
    extern __shared__ char smem[];
    uint32_t sb = s2u(smem);
    int tid = threadIdx.x, wid = tid >> 5, lane = tid & 31;
    int bx = blockIdx.x, by = blockIdx.y, h = blockIdx.z;

    const __nv_bfloat16* Wh = g_Wh + ((size_t)h * MSTR + by * 128) * DIM;
    const __nv_bfloat16* Wl = g_Wl + ((size_t)h * MSTR + by * 128) * DIM;
    const __nv_bfloat16* Xh = g_Xh + ((size_t)h * NSTR + bx * 128) * DIM;
    const __nv_bfloat16* Xl = g_Xl + ((size_t)h * NSTR + bx * 128) * DIM;
    const __nv_bfloat16* Asegs[3] = {Wh, Wl, Wh};
    const __nv_bfloat16* Bsegs[3] = {Xh, Xh, Xl};

    // staging indices: 1024 16B-chunks per matrix per chunk; 4 reps each
    int r0 = tid >> 1;                  // with rep offsets covers 128 rows
    int kc0 = (tid & 1) * 4;            // 16B columns (0..7), 4 per row pass

    int wm0 = (wid >> 2) * 64;          // warp m offset in tile
    int wn0 = (wid & 3) * 32;           // warp n offset in tile

    float acc[4][4][4];
#pragma unroll
    for (int mt = 0; mt < 4; mt++)
#pragma unroll
        for (int nt = 0; nt < 4; nt++)
#pragma unroll
            for (int i = 0; i < 4; i++) acc[mt][nt][i] = 0.f;

#define STAGE(cc)                                                              \
    {                                                                          \
        int seg = (cc) >> 3;                                                   \
        int koff = ((cc) & 7) * 64;                                            \
        const __nv_bfloat16* As = Asegs[seg];                                  \
        const __nv_bfloat16* Bs = Bsegs[seg];                                  \
        uint32_t bb = sb + ((cc) & 1) * SM_BUF;                                \
        _Pragma("unroll")                                                      \
        for (int rep = 0; rep < 4; rep++) {                                    \
            int kc = kc0 + (rep & 3);                                          \
            cp16(bb + SW128(r0 * 128 + kc * 16),                               \
                 As + (size_t)r0 * DIM + koff + kc * 8);                       \
            cp16(bb + 16384 + SW128(r0 * 128 + kc * 16),                       \
                 Bs + (size_t)r0 * DIM + koff + kc * 8);                       \
        }                                                                      \
        asm volatile("cp.async.commit_group;");                                \
    }

    STAGE(0);
    for (int c = 0; c < NCH; c++) {
        if (c + 1 < NCH) {
            STAGE(c + 1);
            asm volatile("cp.async.wait_group 1;");
        } else {
            asm volatile("cp.async.wait_group 0;");
        }
        __syncthreads();

        uint32_t sbA = sb + (c & 1) * SM_BUF;
        uint32_t sbB = sbA + 16384;
#pragma unroll
        for (int ks = 0; ks < 4; ks++) {
            uint32_t a[4][4], b[2][4];
#pragma unroll
            for (int mt = 0; mt < 4; mt++) {
                int row = wm0 + mt * 16 + (lane & 15);
                int colh = lane >> 4;
                ldsm4(a[mt], sbA + SW128(row * 128 + (ks * 2 + colh) * 16));
            }
#pragma unroll
            for (int bt = 0; bt < 2; bt++) {
                int n = wn0 + bt * 16 + ((lane >> 4) << 3) + (lane & 7);
                int khalf = (lane >> 3) & 1;
                ldsm4(b[bt], sbB + SW128(n * 128 + ks * 32 + khalf * 16));
            }
#pragma unroll
            for (int mt = 0; mt < 4; mt++)
#pragma unroll
                for (int nt = 0; nt < 4; nt++)
                    mma_bf16(acc[mt][nt], a[mt], b[nt >> 1] + (nt & 1) * 2);
        }
        __syncthreads();
    }
#undef STAGE

    // write accumulators to Z
    int gr = lane >> 2, gc = (lane & 3) * 2;
    float* Zp = g_Z + (size_t)h * MSTR * NSTR;
#pragma unroll
    for (int mt = 0; mt < 4; mt++) {
        int row0 = by * 128 + wm0 + mt * 16 + gr;
#pragma unroll
        for (int nt = 0; nt < 4; nt++) {
            int col = bx * 128 + wn0 + nt * 8 + gc;
            float2 lo = make_float2(acc[mt][nt][0], acc[mt][nt][1]);
            float2 hi = make_float2(acc[mt][nt][2], acc[mt][nt][3]);
            *(float2*)(Zp + (size_t)row0 * NSTR + col) = lo;
            *(float2*)(Zp + (size_t)(row0 + 8) * NSTR + col) = hi;
        }
    }
}

// ---------------------------------------------------------------------------
// epilogue: Y[h][r][conv*150+c][l] = sum_t Z[h][base+t*150+c][r*32 + l+t-pad]
// ---------------------------------------------------------------------------
__global__ void epilogue_kernel() {
    int r = blockIdx.x, conv = blockIdx.y, h = blockIdx.z;
    int k = conv + 2;
    int pad = (conv >= 2) ? 2 : 1;
    int base = (conv == 0) ? 0 : (conv == 1) ? 300 : (conv == 2) ? 750 : 1350;
    const float* Zp = g_Z + (size_t)h * MSTR * NSTR + r * 32;
    float* out = (h ? g_B : g_A) + (size_t)r * NCC * LP + conv * 150 * LP;
    for (int i = threadIdx.x; i < 150 * 32; i += 256) {
        int c = i >> 5, l = i & 31;
        float v = -1e30f;
        if (l < LSEQ) {
            v = 0.f;
            for (int t = 0; t < k; t++) {
                int lp = l + t - pad;
                if (lp >= 0 && lp < 32)
                    v += Zp[(size_t)(base + t * 150 + c) * NSTR + lp];
            }
        }
        out[c * LP + l] = v;
    }
}

// ---------------------------------------------------------------------------
// combine: one block per pair (b,i,j). out_ch = max(0, max_l(A+B) + bias).
// ---------------------------------------------------------------------------
__global__ void combine_kernel(float* __restrict__ out) {
    int p = blockIdx.x;
    int b = p / 625;
    int rem = p - b * 625;
    int i = rem / 25;
    int j = rem - i * 25;
    const float4* Ap = (const float4*)(g_A + (size_t)(b * 25 + i) * NCC * LP);
    const float4* Bp = (const float4*)(g_B + (size_t)(b * 25 + j) * NCC * LP);

    for (int cc = threadIdx.x; cc < NCC; cc += blockDim.x) {
        float m = -3.0e38f;
#pragma unroll
        for (int l4 = 0; l4 < 8; l4++) {
            float4 a = Ap[cc * 8 + l4];
            float4 bb = Bp[cc * 8 + l4];
            m = fmaxf(m, a.x + bb.x);
            m = fmaxf(m, a.y + bb.y);
            m = fmaxf(m, a.z + bb.z);
            m = fmaxf(m, a.w + bb.w);
        }
        m = fmaxf(0.f, m + g_bias[cc]);
        int conv = cc / 150;
        int c = cc - conv * 150;
        if (c < 75)
            out[p * 300 + conv * 75 + c] = m;
        else
            out[750000 + p * 300 + conv * 75 + (c - 75)] = m;
    }
}

// ---------------------------------------------------------------------------
extern "C" void kernel_launch(void* const* d_in, const int* in_sizes, int n_in,
                              void* d_out, int out_size) {
    const float* s  = (const float*)d_in[0];
    const float* q  = (const float*)d_in[1];
    const float* w2 = (const float*)d_in[2];
    const float* b2 = (const float*)d_in[3];
    const float* w3 = (const float*)d_in[4];
    const float* b3 = (const float*)d_in[5];
    const float* w4 = (const float*)d_in[6];
    const float* b4 = (const float*)d_in[7];
    const float* w5 = (const float*)d_in[8];
    const float* b5 = (const float*)d_in[9];
    float* out = (float*)d_out;

    cudaFuncSetAttribute(gemm_kernel, cudaFuncAttributeMaxDynamicSharedMemorySize,
                         SM_TOTAL);

    wsplit_kernel<<<(2 * MSTR * DIM + 255) / 256, 256>>>(w2, b2, w3, b3, w4, b4, w5, b5);
    xsplit_kernel<<<(2 * NSTR * DIM + 255) / 256, 256>>>(s, q);
    gemm_kernel<<<dim3(NSTR / 128, MSTR / 128, 2), 256, SM_TOTAL>>>();
    epilogue_kernel<<<dim3(NROWS, 4, 2), 256>>>();
    combine_kernel<<<2500, 256>>>(out);
}

// round 6
// speedup vs baseline: 3.7161x; 1.3333x over previous
#include <cuda_runtime.h>
#include <cuda_bf16.h>
#include <cstdint>

// ---------------------------------------------------------------------------
// CNNInteractLayer — mma.sync bf16x3 GEMM-factored implementation.
// conv(concat(s_i,q_j)) = conv_s(s_i) + conv_q(q_j) + bias  (conv is linear).
// Per half: Z[2176x3200] = W[2176x512] @ X[512x3200]^T-view on tensor cores,
// bf16 2-term split stacked along K (K=1536): [Wh,Wl,Wh] . [Xh,Xh,Xl].
// GEMM: 128x128 tile, 4 warps (2x2, warp tile 64x64), double-buffered.
// Then shift-add epilogue + 5x5-tiled pairwise combine.
// ---------------------------------------------------------------------------

#define LSEQ 31
#define DIM 512
#define NROWS 100
#define NCC 600
#define LP 32
#define MTOT 2100
#define MSTR 2176          // 17 * 128
#define NSTR 3200          // 100 rows * 32 = 25 * 128
#define NCH 24             // (3 * 512) / 64 k-chunks

typedef unsigned long long ull;

__device__ __nv_bfloat16 g_Wh[2 * MSTR * DIM];     // [half][m][k]
__device__ __nv_bfloat16 g_Wl[2 * MSTR * DIM];
__device__ __nv_bfloat16 g_Xh[2 * NSTR * DIM];     // [half][n][k]
__device__ __nv_bfloat16 g_Xl[2 * NSTR * DIM];
__device__ float g_Z[2 * (size_t)MSTR * NSTR];
__device__ float g_bias[NCC];
__device__ float g_A[NROWS * NCC * LP];
__device__ float g_B[NROWS * NCC * LP];

// ---------------- PTX helpers ----------------
__device__ __forceinline__ uint32_t s2u(const void* p) {
    uint32_t a;
    asm("{ .reg .u64 t; cvta.to.shared.u64 t, %1; cvt.u32.u64 %0, t; }"
        : "=r"(a) : "l"(p));
    return a;
}
__device__ __forceinline__ void cp16(uint32_t saddr, const void* gptr) {
    asm volatile("cp.async.cg.shared.global [%0], [%1], 16;"
                 :: "r"(saddr), "l"(gptr));
}
__device__ __forceinline__ void ldsm4(uint32_t* r, uint32_t addr) {
    asm volatile("ldmatrix.sync.aligned.m8n8.x4.shared.b16 {%0,%1,%2,%3}, [%4];"
                 : "=r"(r[0]), "=r"(r[1]), "=r"(r[2]), "=r"(r[3]) : "r"(addr));
}
__device__ __forceinline__ void mma_bf16(float* d, const uint32_t* a,
                                         const uint32_t* b) {
    asm volatile(
        "mma.sync.aligned.m16n8k16.row.col.f32.bf16.bf16.f32 "
        "{%0,%1,%2,%3}, {%4,%5,%6,%7}, {%8,%9}, {%0,%1,%2,%3};"
        : "+f"(d[0]), "+f"(d[1]), "+f"(d[2]), "+f"(d[3])
        : "r"(a[0]), "r"(a[1]), "r"(a[2]), "r"(a[3]), "r"(b[0]), "r"(b[1]));
}
#define SW128(x) ((x) ^ (((x) >> 3) & 0x70))

// ---------------------------------------------------------------------------
// wsplit: gather weights into W[h][m][k], split fp32 -> bf16 hi/lo. + bias
// ---------------------------------------------------------------------------
__global__ void wsplit_kernel(const float* __restrict__ w2, const float* __restrict__ b2,
                              const float* __restrict__ w3, const float* __restrict__ b3,
                              const float* __restrict__ w4, const float* __restrict__ b4,
                              const float* __restrict__ w5, const float* __restrict__ b5) {
    int idx = blockIdx.x * blockDim.x + threadIdx.x;
    if (idx < NCC) {
        int conv = idx / 150, c = idx - conv * 150;
        const float* bp = (conv == 0) ? b2 : (conv == 1) ? b3 : (conv == 2) ? b4 : b5;
        g_bias[idx] = bp[c];
    }
    if (idx >= 2 * MSTR * DIM) return;
    int h = idx / (MSTR * DIM);
    int rem = idx - h * (MSTR * DIM);
    int m = rem / DIM;
    int d = rem - m * DIM;
    float v = 0.f;
    if (m < MTOT) {
        int conv = (m < 300) ? 0 : (m < 750) ? 1 : (m < 1350) ? 2 : 3;
        int base = (conv == 0) ? 0 : (conv == 1) ? 300 : (conv == 2) ? 750 : 1350;
        int k = conv + 2;
        int mm = m - base;
        int t = mm / 150, c = mm - t * 150;
        const float* w = (conv == 0) ? w2 : (conv == 1) ? w3 : (conv == 2) ? w4 : w5;
        v = w[(c * 1024 + h * DIM + d) * k + t];
    }
    __nv_bfloat16 hi = __float2bfloat16(v);
    g_Wh[idx] = hi;
    g_Wl[idx] = __float2bfloat16(v - __bfloat162float(hi));
}

// ---------------------------------------------------------------------------
// xsplit: X[h][n=r*32+l][k=d] from inputs (d-contiguous already); l=31 -> 0.
// ---------------------------------------------------------------------------
__global__ void xsplit_kernel(const float* __restrict__ s, const float* __restrict__ q) {
    int idx = blockIdx.x * blockDim.x + threadIdx.x;
    if (idx >= 2 * NSTR * DIM) return;
    int h = idx / (NSTR * DIM);
    int rem = idx - h * (NSTR * DIM);
    int n = rem / DIM;
    int d = rem - n * DIM;
    int r = n >> 5, l = n & 31;
    const float* x = (h ? q : s);
    float v = (l < LSEQ) ? x[((size_t)r * LSEQ + l) * DIM + d] : 0.f;
    __nv_bfloat16 hi = __float2bfloat16(v);
    g_Xh[idx] = hi;
    g_Xl[idx] = __float2bfloat16(v - __bfloat162float(hi));
}

// ---------------------------------------------------------------------------
// gemm: 128x128 block tile, 4 warps (2x2, warp tile 64x64), BK=64,
// double-buffered cp.async, SW128 smem, ldmatrix + mma.sync bf16.
// ---------------------------------------------------------------------------
#define SM_BUF 32768            // per buffer: A 16KB + B 16KB
#define SM_TOTAL 65536

__global__ void __launch_bounds__(128) gemm_kernel() {
    extern __shared__ char smem[];
    uint32_t sb = s2u(smem);
    int tid = threadIdx.x, wid = tid >> 5, lane = tid & 31;
    int bx = blockIdx.x, by = blockIdx.y, h = blockIdx.z;

    const __nv_bfloat16* Wh = g_Wh + ((size_t)h * MSTR + by * 128) * DIM;
    const __nv_bfloat16* Wl = g_Wl + ((size_t)h * MSTR + by * 128) * DIM;
    const __nv_bfloat16* Xh = g_Xh + ((size_t)h * NSTR + bx * 128) * DIM;
    const __nv_bfloat16* Xl = g_Xl + ((size_t)h * NSTR + bx * 128) * DIM;
    const __nv_bfloat16* Asegs[3] = {Wh, Wl, Wh};
    const __nv_bfloat16* Bsegs[3] = {Xh, Xh, Xl};

    int wm0 = (wid >> 1) * 64;          // warp m offset in tile
    int wn0 = (wid & 1) * 64;           // warp n offset in tile

    float acc[4][8][4];
#pragma unroll
    for (int mt = 0; mt < 4; mt++)
#pragma unroll
        for (int nt = 0; nt < 8; nt++)
#pragma unroll
            for (int i = 0; i < 4; i++) acc[mt][nt][i] = 0.f;

    // staging: per matrix 1024 16B-chunks, 128 threads -> 8 reps each
#define STAGE(cc)                                                              \
    {                                                                          \
        int seg = (cc) >> 3;                                                   \
        int koff = ((cc) & 7) * 64;                                            \
        const __nv_bfloat16* As = Asegs[seg];                                  \
        const __nv_bfloat16* Bs = Bsegs[seg];                                  \
        uint32_t bb = sb + ((cc) & 1) * SM_BUF;                                \
        _Pragma("unroll")                                                      \
        for (int rep = 0; rep < 8; rep++) {                                    \
            int cid = rep * 128 + tid;                                         \
            int r = cid >> 3;                                                  \
            int kc = cid & 7;                                                  \
            cp16(bb + SW128(r * 128 + kc * 16),                                \
                 As + (size_t)r * DIM + koff + kc * 8);                        \
            cp16(bb + 16384 + SW128(r * 128 + kc * 16),                        \
                 Bs + (size_t)r * DIM + koff + kc * 8);                        \
        }                                                                      \
        asm volatile("cp.async.commit_group;");                                \
    }

    STAGE(0);
    for (int c = 0; c < NCH; c++) {
        if (c + 1 < NCH) {
            STAGE(c + 1);
            asm volatile("cp.async.wait_group 1;");
        } else {
            asm volatile("cp.async.wait_group 0;");
        }
        __syncthreads();

        uint32_t sbA = sb + (c & 1) * SM_BUF;
        uint32_t sbB = sbA + 16384;
#pragma unroll
        for (int ks = 0; ks < 4; ks++) {
            uint32_t a[4][4], b[4][4];
#pragma unroll
            for (int mt = 0; mt < 4; mt++) {
                int row = wm0 + mt * 16 + (lane & 15);
                int colh = lane >> 4;
                ldsm4(a[mt], sbA + SW128(row * 128 + (ks * 2 + colh) * 16));
            }
#pragma unroll
            for (int bt = 0; bt < 4; bt++) {
                int n = wn0 + bt * 16 + ((lane >> 4) << 3) + (lane & 7);
                int khalf = (lane >> 3) & 1;
                ldsm4(b[bt], sbB + SW128(n * 128 + ks * 32 + khalf * 16));
            }
#pragma unroll
            for (int mt = 0; mt < 4; mt++)
#pragma unroll
                for (int nt = 0; nt < 8; nt++)
                    mma_bf16(acc[mt][nt], a[mt], b[nt >> 1] + (nt & 1) * 2);
        }
        __syncthreads();
    }
#undef STAGE

    // write accumulators to Z
    int gr = lane >> 2, gc = (lane & 3) * 2;
    float* Zp = g_Z + (size_t)h * MSTR * NSTR;
#pragma unroll
    for (int mt = 0; mt < 4; mt++) {
        int row0 = by * 128 + wm0 + mt * 16 + gr;
#pragma unroll
        for (int nt = 0; nt < 8; nt++) {
            int col = bx * 128 + wn0 + nt * 8 + gc;
            float2 lo = make_float2(acc[mt][nt][0], acc[mt][nt][1]);
            float2 hi = make_float2(acc[mt][nt][2], acc[mt][nt][3]);
            *(float2*)(Zp + (size_t)row0 * NSTR + col) = lo;
            *(float2*)(Zp + (size_t)(row0 + 8) * NSTR + col) = hi;
        }
    }
}

// ---------------------------------------------------------------------------
// epilogue: Y[h][r][conv*150+c][l] = sum_t Z[h][base+t*150+c][r*32 + l+t-pad]
// templated on conv for full tap-loop unroll.
// ---------------------------------------------------------------------------
template <int CONV>
__device__ __forceinline__ void epi_body(int r, int h) {
    const int k = CONV + 2;
    const int pad = (CONV >= 2) ? 2 : 1;
    const int base = (CONV == 0) ? 0 : (CONV == 1) ? 300 : (CONV == 2) ? 750 : 1350;
    const float* Zp = g_Z + (size_t)h * MSTR * NSTR + r * 32;
    float* out = (h ? g_B : g_A) + (size_t)r * NCC * LP + CONV * 150 * LP;
    for (int i = threadIdx.x; i < 150 * 32; i += 256) {
        int c = i >> 5, l = i & 31;
        float v = -1e30f;
        if (l < LSEQ) {
            v = 0.f;
#pragma unroll
            for (int t = 0; t < k; t++) {
                int lp = l + t - pad;
                if (lp >= 0 && lp < 32)
                    v += Zp[(size_t)(base + t * 150 + c) * NSTR + lp];
            }
        }
        out[c * LP + l] = v;
    }
}

__global__ void epilogue_kernel() {
    int r = blockIdx.x, h = blockIdx.z;
    switch (blockIdx.y) {
        case 0: epi_body<0>(r, h); break;
        case 1: epi_body<1>(r, h); break;
        case 2: epi_body<2>(r, h); break;
        case 3: epi_body<3>(r, h); break;
    }
}

// ---------------------------------------------------------------------------
// combine: 5x5 pair tiling. Block owns (b, 5 i's, 5 j's); stages 10 rows in
// cc-slabs of 60 through smem (stride-33 pad), serves 25 pairs per load.
// out_ch = max(0, max_l(A+B) + bias).
// ---------------------------------------------------------------------------
#define CSLAB 60
#define CROWPAD 33                       // per-cc padded stride
#define CROWSZ (CSLAB * CROWPAD)         // 1980 floats per staged row
#define CMB_SMEM (2 * 5 * CROWSZ * 4)    // 79200 bytes

__global__ void __launch_bounds__(256) combine_kernel(float* __restrict__ out) {
    extern __shared__ float cs[];
    float* sA = cs;                      // [5][CROWSZ]
    float* sB = cs + 5 * CROWSZ;

    int blk = blockIdx.x;                // 0..99
    int b = blk / 25;
    int rem = blk - b * 25;
    int ig = rem / 5, jg = rem - (rem / 5) * 5;
    int b25 = b * 25;
    int tid = threadIdx.x;

    for (int s = 0; s < NCC / CSLAB; s++) {
        // stage 5 A rows + 5 B rows for this cc slab (float4 global loads)
        for (int idx = tid; idx < 5 * CSLAB * 8; idx += 256) {
            int row = idx / (CSLAB * 8);
            int rest = idx - row * (CSLAB * 8);
            int cc = rest >> 3, l4 = rest & 7;
            size_t goff = ((size_t)(b25 + ig * 5 + row) * NCC + s * CSLAB + cc) * LP
                        + l4 * 4;
            float4 va = *(const float4*)(g_A + goff);
            float* da = sA + row * CROWSZ + cc * CROWPAD + l4 * 4;
            da[0] = va.x; da[1] = va.y; da[2] = va.z; da[3] = va.w;
            size_t goffb = ((size_t)(b25 + jg * 5 + row) * NCC + s * CSLAB + cc) * LP
                         + l4 * 4;
            float4 vb = *(const float4*)(g_B + goffb);
            float* db = sB + row * CROWSZ + cc * CROWPAD + l4 * 4;
            db[0] = vb.x; db[1] = vb.y; db[2] = vb.z; db[3] = vb.w;
        }
        __syncthreads();

        for (int o = tid; o < 25 * CSLAB; o += 256) {
            int pair = o / CSLAB;
            int cci = o - pair * CSLAB;
            int ii = pair / 5, jj = pair - ii * 5;
            const float* ar = sA + ii * CROWSZ + cci * CROWPAD;
            const float* br = sB + jj * CROWSZ + cci * CROWPAD;
            float m = -3.0e38f;
#pragma unroll
            for (int l = 0; l < 32; l++)
                m = fmaxf(m, ar[l] + br[l]);
            int cc = s * CSLAB + cci;
            m = fmaxf(0.f, m + g_bias[cc]);
            int p = b * 625 + (ig * 5 + ii) * 25 + (jg * 5 + jj);
            int conv = cc / 150;
            int c = cc - conv * 150;
            if (c < 75)
                out[p * 300 + conv * 75 + c] = m;
            else
                out[750000 + p * 300 + conv * 75 + (c - 75)] = m;
        }
        __syncthreads();
    }
}

// ---------------------------------------------------------------------------
extern "C" void kernel_launch(void* const* d_in, const int* in_sizes, int n_in,
                              void* d_out, int out_size) {
    const float* s  = (const float*)d_in[0];
    const float* q  = (const float*)d_in[1];
    const float* w2 = (const float*)d_in[2];
    const float* b2 = (const float*)d_in[3];
    const float* w3 = (const float*)d_in[4];
    const float* b3 = (const float*)d_in[5];
    const float* w4 = (const float*)d_in[6];
    const float* b4 = (const float*)d_in[7];
    const float* w5 = (const float*)d_in[8];
    const float* b5 = (const float*)d_in[9];
    float* out = (float*)d_out;

    cudaFuncSetAttribute(gemm_kernel, cudaFuncAttributeMaxDynamicSharedMemorySize,
                         SM_TOTAL);
    cudaFuncSetAttribute(combine_kernel, cudaFuncAttributeMaxDynamicSharedMemorySize,
                         CMB_SMEM);

    wsplit_kernel<<<(2 * MSTR * DIM + 255) / 256, 256>>>(w2, b2, w3, b3, w4, b4, w5, b5);
    xsplit_kernel<<<(2 * NSTR * DIM + 255) / 256, 256>>>(s, q);
    gemm_kernel<<<dim3(NSTR / 128, MSTR / 128, 2), 128, SM_TOTAL>>>();
    epilogue_kernel<<<dim3(NROWS, 4, 2), 256>>>();
    combine_kernel<<<100, 256, CMB_SMEM>>>(out);
}

// round 7
// speedup vs baseline: 3.7851x; 1.0186x over previous
#include <cuda_runtime.h>
#include <cuda_bf16.h>
#include <cstdint>

// ---------------------------------------------------------------------------
// CNNInteractLayer — mma.sync bf16x3 GEMM-factored implementation.
// conv(concat(s_i,q_j)) = conv_s(s_i) + conv_q(q_j) + bias  (conv is linear).
// Per half: Z[2176x3200] = W[2176x512] @ X[512x3200]^T-view on tensor cores.
// bf16 2-term split; the three products (hi*hi + lo*hi + hi*lo) are fused
// into ONE k-chunk pass: stage {Wh,Wl,Xh,Xl} once, reuse fragments across
// products, accumulate all into the same fp32 acc.
// Then shift-add epilogue + 5x5-tiled pairwise combine.
// ---------------------------------------------------------------------------

#define LSEQ 31
#define DIM 512
#define NROWS 100
#define NCC 600
#define LP 32
#define MTOT 2100
#define MSTR 2176          // 17 * 128
#define NSTR 3200          // 100 rows * 32 = 25 * 128
#define NCH 8              // 512 / 64 k-chunks (3 products fused per chunk)

typedef unsigned long long ull;

__device__ __nv_bfloat16 g_Wh[2 * MSTR * DIM];     // [half][m][k]
__device__ __nv_bfloat16 g_Wl[2 * MSTR * DIM];
__device__ __nv_bfloat16 g_Xh[2 * NSTR * DIM];     // [half][n][k]
__device__ __nv_bfloat16 g_Xl[2 * NSTR * DIM];
__device__ float g_Z[2 * (size_t)MSTR * NSTR];
__device__ float g_bias[NCC];
__device__ float g_A[NROWS * NCC * LP];
__device__ float g_B[NROWS * NCC * LP];

// ---------------- PTX helpers ----------------
__device__ __forceinline__ uint32_t s2u(const void* p) {
    uint32_t a;
    asm("{ .reg .u64 t; cvta.to.shared.u64 t, %1; cvt.u32.u64 %0, t; }"
        : "=r"(a) : "l"(p));
    return a;
}
__device__ __forceinline__ void cp16(uint32_t saddr, const void* gptr) {
    asm volatile("cp.async.cg.shared.global [%0], [%1], 16;"
                 :: "r"(saddr), "l"(gptr));
}
__device__ __forceinline__ void ldsm4(uint32_t* r, uint32_t addr) {
    asm volatile("ldmatrix.sync.aligned.m8n8.x4.shared.b16 {%0,%1,%2,%3}, [%4];"
                 : "=r"(r[0]), "=r"(r[1]), "=r"(r[2]), "=r"(r[3]) : "r"(addr));
}
__device__ __forceinline__ void mma_bf16(float* d, const uint32_t* a,
                                         const uint32_t* b) {
    asm volatile(
        "mma.sync.aligned.m16n8k16.row.col.f32.bf16.bf16.f32 "
        "{%0,%1,%2,%3}, {%4,%5,%6,%7}, {%8,%9}, {%0,%1,%2,%3};"
        : "+f"(d[0]), "+f"(d[1]), "+f"(d[2]), "+f"(d[3])
        : "r"(a[0]), "r"(a[1]), "r"(a[2]), "r"(a[3]), "r"(b[0]), "r"(b[1]));
}
#define SW128(x) ((x) ^ (((x) >> 3) & 0x70))

// ---------------------------------------------------------------------------
// wsplit: gather weights into W[h][m][k], split fp32 -> bf16 hi/lo. + bias
// ---------------------------------------------------------------------------
__global__ void wsplit_kernel(const float* __restrict__ w2, const float* __restrict__ b2,
                              const float* __restrict__ w3, const float* __restrict__ b3,
                              const float* __restrict__ w4, const float* __restrict__ b4,
                              const float* __restrict__ w5, const float* __restrict__ b5) {
    int idx = blockIdx.x * blockDim.x + threadIdx.x;
    if (idx < NCC) {
        int conv = idx / 150, c = idx - conv * 150;
        const float* bp = (conv == 0) ? b2 : (conv == 1) ? b3 : (conv == 2) ? b4 : b5;
        g_bias[idx] = bp[c];
    }
    if (idx >= 2 * MSTR * DIM) return;
    int h = idx / (MSTR * DIM);
    int rem = idx - h * (MSTR * DIM);
    int m = rem / DIM;
    int d = rem - m * DIM;
    float v = 0.f;
    if (m < MTOT) {
        int conv = (m < 300) ? 0 : (m < 750) ? 1 : (m < 1350) ? 2 : 3;
        int base = (conv == 0) ? 0 : (conv == 1) ? 300 : (conv == 2) ? 750 : 1350;
        int k = conv + 2;
        int mm = m - base;
        int t = mm / 150, c = mm - t * 150;
        const float* w = (conv == 0) ? w2 : (conv == 1) ? w3 : (conv == 2) ? w4 : w5;
        v = w[(c * 1024 + h * DIM + d) * k + t];
    }
    __nv_bfloat16 hi = __float2bfloat16(v);
    g_Wh[idx] = hi;
    g_Wl[idx] = __float2bfloat16(v - __bfloat162float(hi));
}

// ---------------------------------------------------------------------------
// xsplit: X[h][n=r*32+l][k=d] from inputs (d-contiguous already); l=31 -> 0.
// ---------------------------------------------------------------------------
__global__ void xsplit_kernel(const float* __restrict__ s, const float* __restrict__ q) {
    int idx = blockIdx.x * blockDim.x + threadIdx.x;
    if (idx >= 2 * NSTR * DIM) return;
    int h = idx / (NSTR * DIM);
    int rem = idx - h * (NSTR * DIM);
    int n = rem / DIM;
    int d = rem - n * DIM;
    int r = n >> 5, l = n & 31;
    const float* x = (h ? q : s);
    float v = (l < LSEQ) ? x[((size_t)r * LSEQ + l) * DIM + d] : 0.f;
    __nv_bfloat16 hi = __float2bfloat16(v);
    g_Xh[idx] = hi;
    g_Xl[idx] = __float2bfloat16(v - __bfloat162float(hi));
}

// ---------------------------------------------------------------------------
// gemm: 128x128 block tile, 4 warps (2x2, warp tile 64x64), BK=64,
// double-buffered cp.async. Per chunk stage {Ah, Al, Bh, Bl} (64KB), then
// per ks load 4 fragment sets (16 ldsm) and issue 3 products (96 HMMA),
// all into the same accumulators.
// ---------------------------------------------------------------------------
#define SM_BUF 65536            // per buffer: Ah 16KB | Al 16KB | Bh 16KB | Bl 16KB
#define SM_TOTAL 131072

__global__ void __launch_bounds__(128) gemm_kernel() {
    extern __shared__ char smem[];
    uint32_t sb = s2u(smem);
    int tid = threadIdx.x, wid = tid >> 5, lane = tid & 31;
    int bx = blockIdx.x, by = blockIdx.y, h = blockIdx.z;

    const __nv_bfloat16* Wh = g_Wh + ((size_t)h * MSTR + by * 128) * DIM;
    const __nv_bfloat16* Wl = g_Wl + ((size_t)h * MSTR + by * 128) * DIM;
    const __nv_bfloat16* Xh = g_Xh + ((size_t)h * NSTR + bx * 128) * DIM;
    const __nv_bfloat16* Xl = g_Xl + ((size_t)h * NSTR + bx * 128) * DIM;
    const __nv_bfloat16* mats[4] = {Wh, Wl, Xh, Xl};

    int wm0 = (wid >> 1) * 64;          // warp m offset in tile
    int wn0 = (wid & 1) * 64;           // warp n offset in tile

    float acc[4][8][4];
#pragma unroll
    for (int mt = 0; mt < 4; mt++)
#pragma unroll
        for (int nt = 0; nt < 8; nt++)
#pragma unroll
            for (int i = 0; i < 4; i++) acc[mt][nt][i] = 0.f;

    // staging: 4 matrices x 1024 16B-chunks; 128 threads -> 32 reps each
#define STAGE(cc)                                                              \
    {                                                                          \
        int koff = (cc) * 64;                                                  \
        uint32_t bb = sb + ((cc) & 1) * SM_BUF;                                \
        _Pragma("unroll")                                                      \
        for (int rep = 0; rep < 32; rep++) {                                   \
            int cid = rep * 128 + tid;                                         \
            int mat = cid >> 10;                                               \
            int r = (cid >> 3) & 127;                                          \
            int kc = cid & 7;                                                  \
            cp16(bb + mat * 16384 + SW128(r * 128 + kc * 16),                  \
                 mats[mat] + (size_t)r * DIM + koff + kc * 8);                 \
        }                                                                      \
        asm volatile("cp.async.commit_group;");                                \
    }

    STAGE(0);
    for (int c = 0; c < NCH; c++) {
        if (c + 1 < NCH) {
            STAGE(c + 1);
            asm volatile("cp.async.wait_group 1;");
        } else {
            asm volatile("cp.async.wait_group 0;");
        }
        __syncthreads();

        uint32_t sbAh = sb + (c & 1) * SM_BUF;
        uint32_t sbAl = sbAh + 16384;
        uint32_t sbBh = sbAh + 32768;
        uint32_t sbBl = sbAh + 49152;
#pragma unroll
        for (int ks = 0; ks < 4; ks++) {
            uint32_t ah[4][4], al[4][4], bh[4][4], bl[4][4];
#pragma unroll
            for (int mt = 0; mt < 4; mt++) {
                int row = wm0 + mt * 16 + (lane & 15);
                int colh = lane >> 4;
                uint32_t off = SW128(row * 128 + (ks * 2 + colh) * 16);
                ldsm4(ah[mt], sbAh + off);
                ldsm4(al[mt], sbAl + off);
            }
#pragma unroll
            for (int bt = 0; bt < 4; bt++) {
                int n = wn0 + bt * 16 + ((lane >> 4) << 3) + (lane & 7);
                int khalf = (lane >> 3) & 1;
                uint32_t off = SW128(n * 128 + ks * 32 + khalf * 16);
                ldsm4(bh[bt], sbBh + off);
                ldsm4(bl[bt], sbBl + off);
            }
#pragma unroll
            for (int mt = 0; mt < 4; mt++)
#pragma unroll
                for (int nt = 0; nt < 8; nt++) {
                    mma_bf16(acc[mt][nt], ah[mt], bh[nt >> 1] + (nt & 1) * 2);
                    mma_bf16(acc[mt][nt], al[mt], bh[nt >> 1] + (nt & 1) * 2);
                    mma_bf16(acc[mt][nt], ah[mt], bl[nt >> 1] + (nt & 1) * 2);
                }
        }
        __syncthreads();
    }
#undef STAGE

    // write accumulators to Z
    int gr = lane >> 2, gc = (lane & 3) * 2;
    float* Zp = g_Z + (size_t)h * MSTR * NSTR;
#pragma unroll
    for (int mt = 0; mt < 4; mt++) {
        int row0 = by * 128 + wm0 + mt * 16 + gr;
#pragma unroll
        for (int nt = 0; nt < 8; nt++) {
            int col = bx * 128 + wn0 + nt * 8 + gc;
            float2 lo = make_float2(acc[mt][nt][0], acc[mt][nt][1]);
            float2 hi = make_float2(acc[mt][nt][2], acc[mt][nt][3]);
            *(float2*)(Zp + (size_t)row0 * NSTR + col) = lo;
            *(float2*)(Zp + (size_t)(row0 + 8) * NSTR + col) = hi;
        }
    }
}

// ---------------------------------------------------------------------------
// epilogue: Y[h][r][conv*150+c][l] = sum_t Z[h][base+t*150+c][r*32 + l+t-pad]
// ---------------------------------------------------------------------------
template <int CONV>
__device__ __forceinline__ void epi_body(int r, int h) {
    const int k = CONV + 2;
    const int pad = (CONV >= 2) ? 2 : 1;
    const int base = (CONV == 0) ? 0 : (CONV == 1) ? 300 : (CONV == 2) ? 750 : 1350;
    const float* Zp = g_Z + (size_t)h * MSTR * NSTR + r * 32;
    float* out = (h ? g_B : g_A) + (size_t)r * NCC * LP + CONV * 150 * LP;
    for (int i = threadIdx.x; i < 150 * 32; i += 256) {
        int c = i >> 5, l = i & 31;
        float v = -1e30f;
        if (l < LSEQ) {
            v = 0.f;
#pragma unroll
            for (int t = 0; t < k; t++) {
                int lp = l + t - pad;
                if (lp >= 0 && lp < 32)
                    v += Zp[(size_t)(base + t * 150 + c) * NSTR + lp];
            }
        }
        out[c * LP + l] = v;
    }
}

__global__ void epilogue_kernel() {
    int r = blockIdx.x, h = blockIdx.z;
    switch (blockIdx.y) {
        case 0: epi_body<0>(r, h); break;
        case 1: epi_body<1>(r, h); break;
        case 2: epi_body<2>(r, h); break;
        case 3: epi_body<3>(r, h); break;
    }
}

// ---------------------------------------------------------------------------
// combine: 5x5 pair tiling. Block owns (b, 5 i's, 5 j's); stages 10 rows in
// cc-slabs of 60 through smem (stride-33 pad), serves 25 pairs per load.
// ---------------------------------------------------------------------------
#define CSLAB 60
#define CROWPAD 33
#define CROWSZ (CSLAB * CROWPAD)
#define CMB_SMEM (2 * 5 * CROWSZ * 4)    // 79200 bytes

__global__ void __launch_bounds__(256) combine_kernel(float* __restrict__ out) {
    extern __shared__ float cs[];
    float* sA = cs;
    float* sB = cs + 5 * CROWSZ;

    int blk = blockIdx.x;
    int b = blk / 25;
    int rem = blk - b * 25;
    int ig = rem / 5, jg = rem - (rem / 5) * 5;
    int b25 = b * 25;
    int tid = threadIdx.x;

    for (int s = 0; s < NCC / CSLAB; s++) {
        for (int idx = tid; idx < 5 * CSLAB * 8; idx += 256) {
            int row = idx / (CSLAB * 8);
            int rest = idx - row * (CSLAB * 8);
            int cc = rest >> 3, l4 = rest & 7;
            size_t goff = ((size_t)(b25 + ig * 5 + row) * NCC + s * CSLAB + cc) * LP
                        + l4 * 4;
            float4 va = *(const float4*)(g_A + goff);
            float* da = sA + row * CROWSZ + cc * CROWPAD + l4 * 4;
            da[0] = va.x; da[1] = va.y; da[2] = va.z; da[3] = va.w;
            size_t goffb = ((size_t)(b25 + jg * 5 + row) * NCC + s * CSLAB + cc) * LP
                         + l4 * 4;
            float4 vb = *(const float4*)(g_B + goffb);
            float* db = sB + row * CROWSZ + cc * CROWPAD + l4 * 4;
            db[0] = vb.x; db[1] = vb.y; db[2] = vb.z; db[3] = vb.w;
        }
        __syncthreads();

        for (int o = tid; o < 25 * CSLAB; o += 256) {
            int pair = o / CSLAB;
            int cci = o - pair * CSLAB;
            int ii = pair / 5, jj = pair - ii * 5;
            const float* ar = sA + ii * CROWSZ + cci * CROWPAD;
            const float* br = sB + jj * CROWSZ + cci * CROWPAD;
            float m = -3.0e38f;
#pragma unroll
            for (int l = 0; l < 32; l++)
                m = fmaxf(m, ar[l] + br[l]);
            int cc = s * CSLAB + cci;
            m = fmaxf(0.f, m + g_bias[cc]);
            int p = b * 625 + (ig * 5 + ii) * 25 + (jg * 5 + jj);
            int conv = cc / 150;
            int c = cc - conv * 150;
            if (c < 75)
                out[p * 300 + conv * 75 + c] = m;
            else
                out[750000 + p * 300 + conv * 75 + (c - 75)] = m;
        }
        __syncthreads();
    }
}

// ---------------------------------------------------------------------------
extern "C" void kernel_launch(void* const* d_in, const int* in_sizes, int n_in,
                              void* d_out, int out_size) {
    const float* s  = (const float*)d_in[0];
    const float* q  = (const float*)d_in[1];
    const float* w2 = (const float*)d_in[2];
    const float* b2 = (const float*)d_in[3];
    const float* w3 = (const float*)d_in[4];
    const float* b3 = (const float*)d_in[5];
    const float* w4 = (const float*)d_in[6];
    const float* b4 = (const float*)d_in[7];
    const float* w5 = (const float*)d_in[8];
    const float* b5 = (const float*)d_in[9];
    float* out = (float*)d_out;

    cudaFuncSetAttribute(gemm_kernel, cudaFuncAttributeMaxDynamicSharedMemorySize,
                         SM_TOTAL);
    cudaFuncSetAttribute(combine_kernel, cudaFuncAttributeMaxDynamicSharedMemorySize,
                         CMB_SMEM);

    wsplit_kernel<<<(2 * MSTR * DIM + 255) / 256, 256>>>(w2, b2, w3, b3, w4, b4, w5, b5);
    xsplit_kernel<<<(2 * NSTR * DIM + 255) / 256, 256>>>(s, q);
    gemm_kernel<<<dim3(NSTR / 128, MSTR / 128, 2), 128, SM_TOTAL>>>();
    epilogue_kernel<<<dim3(NROWS, 4, 2), 256>>>();
    combine_kernel<<<100, 256, CMB_SMEM>>>(out);
}

// round 8
// speedup vs baseline: 3.8960x; 1.0293x over previous
#include <cuda_runtime.h>
#include <cuda_bf16.h>
#include <cstdint>

// ---------------------------------------------------------------------------
// CNNInteractLayer — mma.sync bf16x3 GEMM-factored implementation.
// conv(concat(s_i,q_j)) = conv_s(s_i) + conv_q(q_j) + bias  (conv is linear).
// Per half: Z[2176x3200] = W[2176x512] @ X[512x3200]^T-view on tensor cores.
// bf16 2-term split; three products (hi*hi + lo*hi + hi*lo) fused into one
// k-chunk pass. BK=32, 64KB smem/CTA -> 2 CTAs/SM for latency overlap.
// Then shift-add epilogue + 5x5-tiled pairwise combine.
// ---------------------------------------------------------------------------

#define LSEQ 31
#define DIM 512
#define NROWS 100
#define NCC 600
#define LP 32
#define MTOT 2100
#define MSTR 2176          // 17 * 128
#define NSTR 3200          // 100 rows * 32 = 25 * 128
#define NCH 16             // 512 / 32 k-chunks (3 products fused per chunk)

typedef unsigned long long ull;

__device__ __nv_bfloat16 g_Wh[2 * MSTR * DIM];     // [half][m][k]
__device__ __nv_bfloat16 g_Wl[2 * MSTR * DIM];
__device__ __nv_bfloat16 g_Xh[2 * NSTR * DIM];     // [half][n][k]
__device__ __nv_bfloat16 g_Xl[2 * NSTR * DIM];
__device__ float g_Z[2 * (size_t)MSTR * NSTR];
__device__ float g_bias[NCC];
__device__ float g_A[NROWS * NCC * LP];
__device__ float g_B[NROWS * NCC * LP];

// ---------------- PTX helpers ----------------
__device__ __forceinline__ uint32_t s2u(const void* p) {
    uint32_t a;
    asm("{ .reg .u64 t; cvta.to.shared.u64 t, %1; cvt.u32.u64 %0, t; }"
        : "=r"(a) : "l"(p));
    return a;
}
__device__ __forceinline__ void cp16(uint32_t saddr, const void* gptr) {
    asm volatile("cp.async.cg.shared.global [%0], [%1], 16;"
                 :: "r"(saddr), "l"(gptr));
}
__device__ __forceinline__ void ldsm4(uint32_t* r, uint32_t addr) {
    asm volatile("ldmatrix.sync.aligned.m8n8.x4.shared.b16 {%0,%1,%2,%3}, [%4];"
                 : "=r"(r[0]), "=r"(r[1]), "=r"(r[2]), "=r"(r[3]) : "r"(addr));
}
__device__ __forceinline__ void mma_bf16(float* d, const uint32_t* a,
                                         const uint32_t* b) {
    asm volatile(
        "mma.sync.aligned.m16n8k16.row.col.f32.bf16.bf16.f32 "
        "{%0,%1,%2,%3}, {%4,%5,%6,%7}, {%8,%9}, {%0,%1,%2,%3};"
        : "+f"(d[0]), "+f"(d[1]), "+f"(d[2]), "+f"(d[3])
        : "r"(a[0]), "r"(a[1]), "r"(a[2]), "r"(a[3]), "r"(b[0]), "r"(b[1]));
}
#define SW64(x) ((x) ^ (((x) >> 3) & 0x30))

// ---------------------------------------------------------------------------
// wsplit: gather weights into W[h][m][k], split fp32 -> bf16 hi/lo. + bias
// ---------------------------------------------------------------------------
__global__ void wsplit_kernel(const float* __restrict__ w2, const float* __restrict__ b2,
                              const float* __restrict__ w3, const float* __restrict__ b3,
                              const float* __restrict__ w4, const float* __restrict__ b4,
                              const float* __restrict__ w5, const float* __restrict__ b5) {
    int idx = blockIdx.x * blockDim.x + threadIdx.x;
    if (idx < NCC) {
        int conv = idx / 150, c = idx - conv * 150;
        const float* bp = (conv == 0) ? b2 : (conv == 1) ? b3 : (conv == 2) ? b4 : b5;
        g_bias[idx] = bp[c];
    }
    if (idx >= 2 * MSTR * DIM) return;
    int h = idx / (MSTR * DIM);
    int rem = idx - h * (MSTR * DIM);
    int m = rem / DIM;
    int d = rem - m * DIM;
    float v = 0.f;
    if (m < MTOT) {
        int conv = (m < 300) ? 0 : (m < 750) ? 1 : (m < 1350) ? 2 : 3;
        int base = (conv == 0) ? 0 : (conv == 1) ? 300 : (conv == 2) ? 750 : 1350;
        int k = conv + 2;
        int mm = m - base;
        int t = mm / 150, c = mm - t * 150;
        const float* w = (conv == 0) ? w2 : (conv == 1) ? w3 : (conv == 2) ? w4 : w5;
        v = w[(c * 1024 + h * DIM + d) * k + t];
    }
    __nv_bfloat16 hi = __float2bfloat16(v);
    g_Wh[idx] = hi;
    g_Wl[idx] = __float2bfloat16(v - __bfloat162float(hi));
}

// ---------------------------------------------------------------------------
// xsplit: X[h][n=r*32+l][k=d] from inputs (d-contiguous already); l=31 -> 0.
// ---------------------------------------------------------------------------
__global__ void xsplit_kernel(const float* __restrict__ s, const float* __restrict__ q) {
    int idx = blockIdx.x * blockDim.x + threadIdx.x;
    if (idx >= 2 * NSTR * DIM) return;
    int h = idx / (NSTR * DIM);
    int rem = idx - h * (NSTR * DIM);
    int n = rem / DIM;
    int d = rem - n * DIM;
    int r = n >> 5, l = n & 31;
    const float* x = (h ? q : s);
    float v = (l < LSEQ) ? x[((size_t)r * LSEQ + l) * DIM + d] : 0.f;
    __nv_bfloat16 hi = __float2bfloat16(v);
    g_Xh[idx] = hi;
    g_Xl[idx] = __float2bfloat16(v - __bfloat162float(hi));
}

// ---------------------------------------------------------------------------
// gemm: 128x128 block tile, 4 warps (2x2, warp tile 64x64), BK=32 fused,
// double-buffered cp.async, SW64 smem rows (64B), 2 CTAs/SM.
// Per chunk stage {Ah, Al, Bh, Bl} (32KB), per ks load 4 fragment sets
// (16 ldsm) and issue 3 products (96 HMMA) into the same accumulators.
// ---------------------------------------------------------------------------
#define SM_BUF 32768            // per buffer: Ah 8KB | Al 8KB | Bh 8KB | Bl 8KB
#define SM_TOTAL 65536

__global__ void __launch_bounds__(128, 2) gemm_kernel() {
    extern __shared__ char smem[];
    uint32_t sb = s2u(smem);
    int tid = threadIdx.x, wid = tid >> 5, lane = tid & 31;
    int bx = blockIdx.x, by = blockIdx.y, h = blockIdx.z;

    const __nv_bfloat16* Wh = g_Wh + ((size_t)h * MSTR + by * 128) * DIM;
    const __nv_bfloat16* Wl = g_Wl + ((size_t)h * MSTR + by * 128) * DIM;
    const __nv_bfloat16* Xh = g_Xh + ((size_t)h * NSTR + bx * 128) * DIM;
    const __nv_bfloat16* Xl = g_Xl + ((size_t)h * NSTR + bx * 128) * DIM;
    const __nv_bfloat16* mats[4] = {Wh, Wl, Xh, Xl};

    int wm0 = (wid >> 1) * 64;          // warp m offset in tile
    int wn0 = (wid & 1) * 64;           // warp n offset in tile

    float acc[4][8][4];
#pragma unroll
    for (int mt = 0; mt < 4; mt++)
#pragma unroll
        for (int nt = 0; nt < 8; nt++)
#pragma unroll
            for (int i = 0; i < 4; i++) acc[mt][nt][i] = 0.f;

    // staging: 4 mats x 128 rows x 4 16B-chunks = 2048 cp16; 16 per thread
#define STAGE(cc)                                                              \
    {                                                                          \
        int koff = (cc) * 32;                                                  \
        uint32_t bb = sb + ((cc) & 1) * SM_BUF;                                \
        _Pragma("unroll")                                                      \
        for (int rep = 0; rep < 16; rep++) {                                   \
            int cid = rep * 128 + tid;                                         \
            int mat = cid >> 9;                                                \
            int r = (cid >> 2) & 127;                                          \
            int kc = cid & 3;                                                  \
            cp16(bb + mat * 8192 + SW64(r * 64 + kc * 16),                     \
                 mats[mat] + (size_t)r * DIM + koff + kc * 8);                 \
        }                                                                      \
        asm volatile("cp.async.commit_group;");                                \
    }

    STAGE(0);
    for (int c = 0; c < NCH; c++) {
        if (c + 1 < NCH) {
            STAGE(c + 1);
            asm volatile("cp.async.wait_group 1;");
        } else {
            asm volatile("cp.async.wait_group 0;");
        }
        __syncthreads();

        uint32_t sbAh = sb + (c & 1) * SM_BUF;
        uint32_t sbAl = sbAh + 8192;
        uint32_t sbBh = sbAh + 16384;
        uint32_t sbBl = sbAh + 24576;
#pragma unroll
        for (int ks = 0; ks < 2; ks++) {
            uint32_t ah[4][4], al[4][4], bh[4][4], bl[4][4];
#pragma unroll
            for (int mt = 0; mt < 4; mt++) {
                int row = wm0 + mt * 16 + (lane & 15);
                int colh = lane >> 4;
                uint32_t off = SW64(row * 64 + (ks * 2 + colh) * 16);
                ldsm4(ah[mt], sbAh + off);
                ldsm4(al[mt], sbAl + off);
            }
#pragma unroll
            for (int bt = 0; bt < 4; bt++) {
                int n = wn0 + bt * 16 + ((lane >> 4) << 3) + (lane & 7);
                int khalf = (lane >> 3) & 1;
                uint32_t off = SW64(n * 64 + (ks * 2 + khalf) * 16);
                ldsm4(bh[bt], sbBh + off);
                ldsm4(bl[bt], sbBl + off);
            }
#pragma unroll
            for (int mt = 0; mt < 4; mt++)
#pragma unroll
                for (int nt = 0; nt < 8; nt++) {
                    mma_bf16(acc[mt][nt], ah[mt], bh[nt >> 1] + (nt & 1) * 2);
                    mma_bf16(acc[mt][nt], al[mt], bh[nt >> 1] + (nt & 1) * 2);
                    mma_bf16(acc[mt][nt], ah[mt], bl[nt >> 1] + (nt & 1) * 2);
                }
        }
        __syncthreads();
    }
#undef STAGE

    // write accumulators to Z
    int gr = lane >> 2, gc = (lane & 3) * 2;
    float* Zp = g_Z + (size_t)h * MSTR * NSTR;
#pragma unroll
    for (int mt = 0; mt < 4; mt++) {
        int row0 = by * 128 + wm0 + mt * 16 + gr;
#pragma unroll
        for (int nt = 0; nt < 8; nt++) {
            int col = bx * 128 + wn0 + nt * 8 + gc;
            float2 lo = make_float2(acc[mt][nt][0], acc[mt][nt][1]);
            float2 hi = make_float2(acc[mt][nt][2], acc[mt][nt][3]);
            *(float2*)(Zp + (size_t)row0 * NSTR + col) = lo;
            *(float2*)(Zp + (size_t)(row0 + 8) * NSTR + col) = hi;
        }
    }
}

// ---------------------------------------------------------------------------
// epilogue: Y[h][r][conv*150+c][l] = sum_t Z[h][base+t*150+c][r*32 + l+t-pad]
// ---------------------------------------------------------------------------
template <int CONV>
__device__ __forceinline__ void epi_body(int r, int h) {
    const int k = CONV + 2;
    const int pad = (CONV >= 2) ? 2 : 1;
    const int base = (CONV == 0) ? 0 : (CONV == 1) ? 300 : (CONV == 2) ? 750 : 1350;
    const float* Zp = g_Z + (size_t)h * MSTR * NSTR + r * 32;
    float* out = (h ? g_B : g_A) + (size_t)r * NCC * LP + CONV * 150 * LP;
    for (int i = threadIdx.x; i < 150 * 32; i += 256) {
        int c = i >> 5, l = i & 31;
        float v = -1e30f;
        if (l < LSEQ) {
            v = 0.f;
#pragma unroll
            for (int t = 0; t < k; t++) {
                int lp = l + t - pad;
                if (lp >= 0 && lp < 32)
                    v += Zp[(size_t)(base + t * 150 + c) * NSTR + lp];
            }
        }
        out[c * LP + l] = v;
    }
}

__global__ void epilogue_kernel() {
    int r = blockIdx.x, h = blockIdx.z;
    switch (blockIdx.y) {
        case 0: epi_body<0>(r, h); break;
        case 1: epi_body<1>(r, h); break;
        case 2: epi_body<2>(r, h); break;
        case 3: epi_body<3>(r, h); break;
    }
}

// ---------------------------------------------------------------------------
// combine: 5x5 pair tiling. Block owns (b, 5 i's, 5 j's); stages 10 rows in
// cc-slabs of 60 through smem (stride-33 pad), serves 25 pairs per load.
// ---------------------------------------------------------------------------
#define CSLAB 60
#define CROWPAD 33
#define CROWSZ (CSLAB * CROWPAD)
#define CMB_SMEM (2 * 5 * CROWSZ * 4)    // 79200 bytes

__global__ void __launch_bounds__(256) combine_kernel(float* __restrict__ out) {
    extern __shared__ float cs[];
    float* sA = cs;
    float* sB = cs + 5 * CROWSZ;

    int blk = blockIdx.x;
    int b = blk / 25;
    int rem = blk - b * 25;
    int ig = rem / 5, jg = rem - (rem / 5) * 5;
    int b25 = b * 25;
    int tid = threadIdx.x;

    for (int s = 0; s < NCC / CSLAB; s++) {
        for (int idx = tid; idx < 5 * CSLAB * 8; idx += 256) {
            int row = idx / (CSLAB * 8);
            int rest = idx - row * (CSLAB * 8);
            int cc = rest >> 3, l4 = rest & 7;
            size_t goff = ((size_t)(b25 + ig * 5 + row) * NCC + s * CSLAB + cc) * LP
                        + l4 * 4;
            float4 va = *(const float4*)(g_A + goff);
            float* da = sA + row * CROWSZ + cc * CROWPAD + l4 * 4;
            da[0] = va.x; da[1] = va.y; da[2] = va.z; da[3] = va.w;
            size_t goffb = ((size_t)(b25 + jg * 5 + row) * NCC + s * CSLAB + cc) * LP
                         + l4 * 4;
            float4 vb = *(const float4*)(g_B + goffb);
            float* db = sB + row * CROWSZ + cc * CROWPAD + l4 * 4;
            db[0] = vb.x; db[1] = vb.y; db[2] = vb.z; db[3] = vb.w;
        }
        __syncthreads();

        for (int o = tid; o < 25 * CSLAB; o += 256) {
            int pair = o / CSLAB;
            int cci = o - pair * CSLAB;
            int ii = pair / 5, jj = pair - ii * 5;
            const float* ar = sA + ii * CROWSZ + cci * CROWPAD;
            const float* br = sB + jj * CROWSZ + cci * CROWPAD;
            float m = -3.0e38f;
#pragma unroll
            for (int l = 0; l < 32; l++)
                m = fmaxf(m, ar[l] + br[l]);
            int cc = s * CSLAB + cci;
            m = fmaxf(0.f, m + g_bias[cc]);
            int p = b * 625 + (ig * 5 + ii) * 25 + (jg * 5 + jj);
            int conv = cc / 150;
            int c = cc - conv * 150;
            if (c < 75)
                out[p * 300 + conv * 75 + c] = m;
            else
                out[750000 + p * 300 + conv * 75 + (c - 75)] = m;
        }
        __syncthreads();
    }
}

// ---------------------------------------------------------------------------
extern "C" void kernel_launch(void* const* d_in, const int* in_sizes, int n_in,
                              void* d_out, int out_size) {
    const float* s  = (const float*)d_in[0];
    const float* q  = (const float*)d_in[1];
    const float* w2 = (const float*)d_in[2];
    const float* b2 = (const float*)d_in[3];
    const float* w3 = (const float*)d_in[4];
    const float* b3 = (const float*)d_in[5];
    const float* w4 = (const float*)d_in[6];
    const float* b4 = (const float*)d_in[7];
    const float* w5 = (const float*)d_in[8];
    const float* b5 = (const float*)d_in[9];
    float* out = (float*)d_out;

    cudaFuncSetAttribute(gemm_kernel, cudaFuncAttributeMaxDynamicSharedMemorySize,
                         SM_TOTAL);
    cudaFuncSetAttribute(combine_kernel, cudaFuncAttributeMaxDynamicSharedMemorySize,
                         CMB_SMEM);

    wsplit_kernel<<<(2 * MSTR * DIM + 255) / 256, 256>>>(w2, b2, w3, b3, w4, b4, w5, b5);
    xsplit_kernel<<<(2 * NSTR * DIM + 255) / 256, 256>>>(s, q);
    gemm_kernel<<<dim3(NSTR / 128, MSTR / 128, 2), 128, SM_TOTAL>>>();
    epilogue_kernel<<<dim3(NROWS, 4, 2), 256>>>();
    combine_kernel<<<100, 256, CMB_SMEM>>>(out);
}

// round 9
// speedup vs baseline: 4.8355x; 1.2412x over previous
#include <cuda_runtime.h>
#include <cuda_fp16.h>
#include <cstdint>

// ---------------------------------------------------------------------------
// CNNInteractLayer — mma.sync fp16x2 GEMM-factored implementation.
// conv(concat(s_i,q_j)) = conv_s(s_i) + conv_q(q_j) + bias  (conv is linear).
// Per half: Z[2176x3200] = W[2176x512] @ X[512x3200]^T-view on tensor cores.
// fp16 2-term split on W only: (wh + wl) . fp16(x) = w . fp16(x) exactly;
// residual error w.(x - fp16(x)) ~ 2^-12 relative. fp32 accumulation.
// Then shift-add epilogue + 5x5-tiled pairwise combine.
// ---------------------------------------------------------------------------

#define LSEQ 31
#define DIM 512
#define NROWS 100
#define NCC 600
#define LP 32
#define MTOT 2100
#define MSTR 2176          // 17 * 128
#define NSTR 3200          // 100 rows * 32 = 25 * 128
#define NCH 8              // 512 / 64 k-chunks (2 products fused per chunk)

typedef unsigned long long ull;

__device__ __half g_Wh[2 * MSTR * DIM];            // [half][m][k]
__device__ __half g_Wl[2 * MSTR * DIM];
__device__ __half g_Xh[2 * NSTR * DIM];            // [half][n][k]
__device__ float g_Z[2 * (size_t)MSTR * NSTR];
__device__ float g_bias[NCC];
__device__ float g_A[NROWS * NCC * LP];
__device__ float g_B[NROWS * NCC * LP];

// ---------------- PTX helpers ----------------
__device__ __forceinline__ uint32_t s2u(const void* p) {
    uint32_t a;
    asm("{ .reg .u64 t; cvta.to.shared.u64 t, %1; cvt.u32.u64 %0, t; }"
        : "=r"(a) : "l"(p));
    return a;
}
__device__ __forceinline__ void cp16(uint32_t saddr, const void* gptr) {
    asm volatile("cp.async.cg.shared.global [%0], [%1], 16;"
                 :: "r"(saddr), "l"(gptr));
}
__device__ __forceinline__ void ldsm4(uint32_t* r, uint32_t addr) {
    asm volatile("ldmatrix.sync.aligned.m8n8.x4.shared.b16 {%0,%1,%2,%3}, [%4];"
                 : "=r"(r[0]), "=r"(r[1]), "=r"(r[2]), "=r"(r[3]) : "r"(addr));
}
__device__ __forceinline__ void mma_f16(float* d, const uint32_t* a,
                                        const uint32_t* b) {
    asm volatile(
        "mma.sync.aligned.m16n8k16.row.col.f32.f16.f16.f32 "
        "{%0,%1,%2,%3}, {%4,%5,%6,%7}, {%8,%9}, {%0,%1,%2,%3};"
        : "+f"(d[0]), "+f"(d[1]), "+f"(d[2]), "+f"(d[3])
        : "r"(a[0]), "r"(a[1]), "r"(a[2]), "r"(a[3]), "r"(b[0]), "r"(b[1]));
}
#define SW128(x) ((x) ^ (((x) >> 3) & 0x70))

// ---------------------------------------------------------------------------
// wsplit: gather weights into W[h][m][k], split fp32 -> fp16 hi/lo. + bias
// ---------------------------------------------------------------------------
__global__ void wsplit_kernel(const float* __restrict__ w2, const float* __restrict__ b2,
                              const float* __restrict__ w3, const float* __restrict__ b3,
                              const float* __restrict__ w4, const float* __restrict__ b4,
                              const float* __restrict__ w5, const float* __restrict__ b5) {
    int idx = blockIdx.x * blockDim.x + threadIdx.x;
    if (idx < NCC) {
        int conv = idx / 150, c = idx - conv * 150;
        const float* bp = (conv == 0) ? b2 : (conv == 1) ? b3 : (conv == 2) ? b4 : b5;
        g_bias[idx] = bp[c];
    }
    if (idx >= 2 * MSTR * DIM) return;
    int h = idx / (MSTR * DIM);
    int rem = idx - h * (MSTR * DIM);
    int m = rem / DIM;
    int d = rem - m * DIM;
    float v = 0.f;
    if (m < MTOT) {
        int conv = (m < 300) ? 0 : (m < 750) ? 1 : (m < 1350) ? 2 : 3;
        int base = (conv == 0) ? 0 : (conv == 1) ? 300 : (conv == 2) ? 750 : 1350;
        int k = conv + 2;
        int mm = m - base;
        int t = mm / 150, c = mm - t * 150;
        const float* w = (conv == 0) ? w2 : (conv == 1) ? w3 : (conv == 2) ? w4 : w5;
        v = w[(c * 1024 + h * DIM + d) * k + t];
    }
    __half hi = __float2half(v);
    g_Wh[idx] = hi;
    g_Wl[idx] = __float2half(v - __half2float(hi));
}

// ---------------------------------------------------------------------------
// xsplit: X[h][n=r*32+l][k=d] fp16 from inputs (d-contiguous); l=31 -> 0.
// ---------------------------------------------------------------------------
__global__ void xsplit_kernel(const float* __restrict__ s, const float* __restrict__ q) {
    int idx = blockIdx.x * blockDim.x + threadIdx.x;
    if (idx >= 2 * NSTR * DIM) return;
    int h = idx / (NSTR * DIM);
    int rem = idx - h * (NSTR * DIM);
    int n = rem / DIM;
    int d = rem - n * DIM;
    int r = n >> 5, l = n & 31;
    const float* x = (h ? q : s);
    float v = (l < LSEQ) ? x[((size_t)r * LSEQ + l) * DIM + d] : 0.f;
    g_Xh[idx] = __float2half(v);
}

// ---------------------------------------------------------------------------
// gemm: 128x128 block tile, 4 warps (2x2, warp tile 64x64), BK=64 fused,
// double-buffered cp.async, SW128 smem rows (128B), 2 CTAs/SM (96KB smem).
// Per chunk stage {Ah, Al, Bh} (48KB); per ks load 3 fragment sets
// (12 ldsm) and issue 2 products (64 HMMA) into the same accumulators.
// ---------------------------------------------------------------------------
#define SM_BUF 49152            // per buffer: Ah 16KB | Al 16KB | Bh 16KB
#define SM_TOTAL 98304

__global__ void __launch_bounds__(128, 2) gemm_kernel() {
    extern __shared__ char smem[];
    uint32_t sb = s2u(smem);
    int tid = threadIdx.x, wid = tid >> 5, lane = tid & 31;
    int bx = blockIdx.x, by = blockIdx.y, h = blockIdx.z;

    const __half* Wh = g_Wh + ((size_t)h * MSTR + by * 128) * DIM;
    const __half* Wl = g_Wl + ((size_t)h * MSTR + by * 128) * DIM;
    const __half* Xh = g_Xh + ((size_t)h * NSTR + bx * 128) * DIM;
    const __half* mats[3] = {Wh, Wl, Xh};

    int wm0 = (wid >> 1) * 64;          // warp m offset in tile
    int wn0 = (wid & 1) * 64;           // warp n offset in tile

    float acc[4][8][4];
#pragma unroll
    for (int mt = 0; mt < 4; mt++)
#pragma unroll
        for (int nt = 0; nt < 8; nt++)
#pragma unroll
            for (int i = 0; i < 4; i++) acc[mt][nt][i] = 0.f;

    // staging: 3 mats x 128 rows x 8 16B-chunks = 3072 cp16; 24 per thread
#define STAGE(cc)                                                              \
    {                                                                          \
        int koff = (cc) * 64;                                                  \
        uint32_t bb = sb + ((cc) & 1) * SM_BUF;                                \
        _Pragma("unroll")                                                      \
        for (int rep = 0; rep < 24; rep++) {                                   \
            int cid = rep * 128 + tid;                                         \
            int mat = cid >> 10;                                               \
            int r = (cid >> 3) & 127;                                          \
            int kc = cid & 7;                                                  \
            cp16(bb + mat * 16384 + SW128(r * 128 + kc * 16),                  \
                 mats[mat] + (size_t)r * DIM + koff + kc * 8);                 \
        }                                                                      \
        asm volatile("cp.async.commit_group;");                                \
    }

    STAGE(0);
    for (int c = 0; c < NCH; c++) {
        if (c + 1 < NCH) {
            STAGE(c + 1);
            asm volatile("cp.async.wait_group 1;");
        } else {
            asm volatile("cp.async.wait_group 0;");
        }
        __syncthreads();

        uint32_t sbAh = sb + (c & 1) * SM_BUF;
        uint32_t sbAl = sbAh + 16384;
        uint32_t sbBh = sbAh + 32768;
#pragma unroll
        for (int ks = 0; ks < 4; ks++) {
            uint32_t ah[4][4], al[4][4], bh[4][4];
#pragma unroll
            for (int mt = 0; mt < 4; mt++) {
                int row = wm0 + mt * 16 + (lane & 15);
                int colh = lane >> 4;
                uint32_t off = SW128(row * 128 + (ks * 2 + colh) * 16);
                ldsm4(ah[mt], sbAh + off);
                ldsm4(al[mt], sbAl + off);
            }
#pragma unroll
            for (int bt = 0; bt < 4; bt++) {
                int n = wn0 + bt * 16 + ((lane >> 4) << 3) + (lane & 7);
                int khalf = (lane >> 3) & 1;
                uint32_t off = SW128(n * 128 + ks * 32 + khalf * 16);
                ldsm4(bh[bt], sbBh + off);
            }
#pragma unroll
            for (int mt = 0; mt < 4; mt++)
#pragma unroll
                for (int nt = 0; nt < 8; nt++) {
                    mma_f16(acc[mt][nt], ah[mt], bh[nt >> 1] + (nt & 1) * 2);
                    mma_f16(acc[mt][nt], al[mt], bh[nt >> 1] + (nt & 1) * 2);
                }
        }
        __syncthreads();
    }
#undef STAGE

    // write accumulators to Z
    int gr = lane >> 2, gc = (lane & 3) * 2;
    float* Zp = g_Z + (size_t)h * MSTR * NSTR;
#pragma unroll
    for (int mt = 0; mt < 4; mt++) {
        int row0 = by * 128 + wm0 + mt * 16 + gr;
#pragma unroll
        for (int nt = 0; nt < 8; nt++) {
            int col = bx * 128 + wn0 + nt * 8 + gc;
            float2 lo = make_float2(acc[mt][nt][0], acc[mt][nt][1]);
            float2 hi = make_float2(acc[mt][nt][2], acc[mt][nt][3]);
            *(float2*)(Zp + (size_t)row0 * NSTR + col) = lo;
            *(float2*)(Zp + (size_t)(row0 + 8) * NSTR + col) = hi;
        }
    }
}

// ---------------------------------------------------------------------------
// epilogue: Y[h][r][conv*150+c][l] = sum_t Z[h][base+t*150+c][r*32 + l+t-pad]
// ---------------------------------------------------------------------------
template <int CONV>
__device__ __forceinline__ void epi_body(int r, int h) {
    const int k = CONV + 2;
    const int pad = (CONV >= 2) ? 2 : 1;
    const int base = (CONV == 0) ? 0 : (CONV == 1) ? 300 : (CONV == 2) ? 750 : 1350;
    const float* Zp = g_Z + (size_t)h * MSTR * NSTR + r * 32;
    float* out = (h ? g_B : g_A) + (size_t)r * NCC * LP + CONV * 150 * LP;
    for (int i = threadIdx.x; i < 150 * 32; i += 256) {
        int c = i >> 5, l = i & 31;
        float v = -1e30f;
        if (l < LSEQ) {
            v = 0.f;
#pragma unroll
            for (int t = 0; t < k; t++) {
                int lp = l + t - pad;
                if (lp >= 0 && lp < 32)
                    v += Zp[(size_t)(base + t * 150 + c) * NSTR + lp];
            }
        }
        out[c * LP + l] = v;
    }
}

__global__ void epilogue_kernel() {
    int r = blockIdx.x, h = blockIdx.z;
    switch (blockIdx.y) {
        case 0: epi_body<0>(r, h); break;
        case 1: epi_body<1>(r, h); break;
        case 2: epi_body<2>(r, h); break;
        case 3: epi_body<3>(r, h); break;
    }
}

// ---------------------------------------------------------------------------
// combine: 5x5 pair tiling. Block owns (b, 5 i's, 5 j's); stages 10 rows in
// cc-slabs of 60 through smem (stride-33 pad), serves 25 pairs per load.
// ---------------------------------------------------------------------------
#define CSLAB 60
#define CROWPAD 33
#define CROWSZ (CSLAB * CROWPAD)
#define CMB_SMEM (2 * 5 * CROWSZ * 4)    // 79200 bytes

__global__ void __launch_bounds__(256) combine_kernel(float* __restrict__ out) {
    extern __shared__ float cs[];
    float* sA = cs;
    float* sB = cs + 5 * CROWSZ;

    int blk = blockIdx.x;
    int b = blk / 25;
    int rem = blk - b * 25;
    int ig = rem / 5, jg = rem - (rem / 5) * 5;
    int b25 = b * 25;
    int tid = threadIdx.x;

    for (int s = 0; s < NCC / CSLAB; s++) {
        for (int idx = tid; idx < 5 * CSLAB * 8; idx += 256) {
            int row = idx / (CSLAB * 8);
            int rest = idx - row * (CSLAB * 8);
            int cc = rest >> 3, l4 = rest & 7;
            size_t goff = ((size_t)(b25 + ig * 5 + row) * NCC + s * CSLAB + cc) * LP
                        + l4 * 4;
            float4 va = *(const float4*)(g_A + goff);
            float* da = sA + row * CROWSZ + cc * CROWPAD + l4 * 4;
            da[0] = va.x; da[1] = va.y; da[2] = va.z; da[3] = va.w;
            size_t goffb = ((size_t)(b25 + jg * 5 + row) * NCC + s * CSLAB + cc) * LP
                         + l4 * 4;
            float4 vb = *(const float4*)(g_B + goffb);
            float* db = sB + row * CROWSZ + cc * CROWPAD + l4 * 4;
            db[0] = vb.x; db[1] = vb.y; db[2] = vb.z; db[3] = vb.w;
        }
        __syncthreads();

        for (int o = tid; o < 25 * CSLAB; o += 256) {
            int pair = o / CSLAB;
            int cci = o - pair * CSLAB;
            int ii = pair / 5, jj = pair - ii * 5;
            const float* ar = sA + ii * CROWSZ + cci * CROWPAD;
            const float* br = sB + jj * CROWSZ + cci * CROWPAD;
            float m = -3.0e38f;
#pragma unroll
            for (int l = 0; l < 32; l++)
                m = fmaxf(m, ar[l] + br[l]);
            int cc = s * CSLAB + cci;
            m = fmaxf(0.f, m + g_bias[cc]);
            int p = b * 625 + (ig * 5 + ii) * 25 + (jg * 5 + jj);
            int conv = cc / 150;
            int c = cc - conv * 150;
            if (c < 75)
                out[p * 300 + conv * 75 + c] = m;
            else
                out[750000 + p * 300 + conv * 75 + (c - 75)] = m;
        }
        __syncthreads();
    }
}

// ---------------------------------------------------------------------------
extern "C" void kernel_launch(void* const* d_in, const int* in_sizes, int n_in,
                              void* d_out, int out_size) {
    const float* s  = (const float*)d_in[0];
    const float* q  = (const float*)d_in[1];
    const float* w2 = (const float*)d_in[2];
    const float* b2 = (const float*)d_in[3];
    const float* w3 = (const float*)d_in[4];
    const float* b3 = (const float*)d_in[5];
    const float* w4 = (const float*)d_in[6];
    const float* b4 = (const float*)d_in[7];
    const float* w5 = (const float*)d_in[8];
    const float* b5 = (const float*)d_in[9];
    float* out = (float*)d_out;

    cudaFuncSetAttribute(gemm_kernel, cudaFuncAttributeMaxDynamicSharedMemorySize,
                         SM_TOTAL);
    cudaFuncSetAttribute(combine_kernel, cudaFuncAttributeMaxDynamicSharedMemorySize,
                         CMB_SMEM);

    wsplit_kernel<<<(2 * MSTR * DIM + 255) / 256, 256>>>(w2, b2, w3, b3, w4, b4, w5, b5);
    xsplit_kernel<<<(2 * NSTR * DIM + 255) / 256, 256>>>(s, q);
    gemm_kernel<<<dim3(NSTR / 128, MSTR / 128, 2), 128, SM_TOTAL>>>();
    epilogue_kernel<<<dim3(NROWS, 4, 2), 256>>>();
    combine_kernel<<<100, 256, CMB_SMEM>>>(out);
}

// round 10
// speedup vs baseline: 5.9008x; 1.2203x over previous
#include <cuda_runtime.h>
#include <cuda_fp16.h>
#include <cstdint>

// ---------------------------------------------------------------------------
// CNNInteractLayer — mma.sync fp16 GEMM-factored implementation.
// conv(concat(s_i,q_j)) = conv_s(s_i) + conv_q(q_j) + bias  (conv is linear).
// Per half: Z[2176x3200] = W[2176x512] @ X[512x3200]^T-view on tensor cores,
// single-product fp16 (values are N(0,1)-scale; quantization ~2^-12 relative,
// measured ~2e-4 << 1e-3 gate), fp32 accumulation.
// Then shift-add epilogue + 5x5-tiled pairwise combine.
// ---------------------------------------------------------------------------

#define LSEQ 31
#define DIM 512
#define NROWS 100
#define NCC 600
#define LP 32
#define MTOT 2100
#define MSTR 2176          // 17 * 128
#define NSTR 3200          // 100 rows * 32 = 25 * 128
#define NCH 8              // 512 / 64 k-chunks

typedef unsigned long long ull;

__device__ __half g_Wh[2 * MSTR * DIM];            // [half][m][k]
__device__ __half g_Xh[2 * NSTR * DIM];            // [half][n][k]
__device__ float g_Z[2 * (size_t)MSTR * NSTR];
__device__ float g_bias[NCC];
__device__ float g_A[NROWS * NCC * LP];
__device__ float g_B[NROWS * NCC * LP];

// ---------------- PTX helpers ----------------
__device__ __forceinline__ uint32_t s2u(const void* p) {
    uint32_t a;
    asm("{ .reg .u64 t; cvta.to.shared.u64 t, %1; cvt.u32.u64 %0, t; }"
        : "=r"(a) : "l"(p));
    return a;
}
__device__ __forceinline__ void cp16(uint32_t saddr, const void* gptr) {
    asm volatile("cp.async.cg.shared.global [%0], [%1], 16;"
                 :: "r"(saddr), "l"(gptr));
}
__device__ __forceinline__ void ldsm4(uint32_t* r, uint32_t addr) {
    asm volatile("ldmatrix.sync.aligned.m8n8.x4.shared.b16 {%0,%1,%2,%3}, [%4];"
                 : "=r"(r[0]), "=r"(r[1]), "=r"(r[2]), "=r"(r[3]) : "r"(addr));
}
__device__ __forceinline__ void mma_f16(float* d, const uint32_t* a,
                                        const uint32_t* b) {
    asm volatile(
        "mma.sync.aligned.m16n8k16.row.col.f32.f16.f16.f32 "
        "{%0,%1,%2,%3}, {%4,%5,%6,%7}, {%8,%9}, {%0,%1,%2,%3};"
        : "+f"(d[0]), "+f"(d[1]), "+f"(d[2]), "+f"(d[3])
        : "r"(a[0]), "r"(a[1]), "r"(a[2]), "r"(a[3]), "r"(b[0]), "r"(b[1]));
}
#define SW128(x) ((x) ^ (((x) >> 3) & 0x70))

// ---------------------------------------------------------------------------
// wsplit: gather weights into W[h][m][k] fp16. + bias
// w_k layout: (150, 1024, k) -> w[(c*1024 + cin)*k + t]; m = base + t*150 + c
// ---------------------------------------------------------------------------
__global__ void wsplit_kernel(const float* __restrict__ w2, const float* __restrict__ b2,
                              const float* __restrict__ w3, const float* __restrict__ b3,
                              const float* __restrict__ w4, const float* __restrict__ b4,
                              const float* __restrict__ w5, const float* __restrict__ b5) {
    int idx = blockIdx.x * blockDim.x + threadIdx.x;
    if (idx < NCC) {
        int conv = idx / 150, c = idx - conv * 150;
        const float* bp = (conv == 0) ? b2 : (conv == 1) ? b3 : (conv == 2) ? b4 : b5;
        g_bias[idx] = bp[c];
    }
    if (idx >= 2 * MSTR * DIM) return;
    int h = idx / (MSTR * DIM);
    int rem = idx - h * (MSTR * DIM);
    int m = rem / DIM;
    int d = rem - m * DIM;
    float v = 0.f;
    if (m < MTOT) {
        int conv = (m < 300) ? 0 : (m < 750) ? 1 : (m < 1350) ? 2 : 3;
        int base = (conv == 0) ? 0 : (conv == 1) ? 300 : (conv == 2) ? 750 : 1350;
        int k = conv + 2;
        int mm = m - base;
        int t = mm / 150, c = mm - t * 150;
        const float* w = (conv == 0) ? w2 : (conv == 1) ? w3 : (conv == 2) ? w4 : w5;
        v = w[(c * 1024 + h * DIM + d) * k + t];
    }
    g_Wh[idx] = __float2half(v);
}

// ---------------------------------------------------------------------------
// xsplit: X[h][n=r*32+l][k=d] fp16 from inputs (d-contiguous); l=31 -> 0.
// ---------------------------------------------------------------------------
__global__ void xsplit_kernel(const float* __restrict__ s, const float* __restrict__ q) {
    int idx = blockIdx.x * blockDim.x + threadIdx.x;
    if (idx >= 2 * NSTR * DIM) return;
    int h = idx / (NSTR * DIM);
    int rem = idx - h * (NSTR * DIM);
    int n = rem / DIM;
    int d = rem - n * DIM;
    int r = n >> 5, l = n & 31;
    const float* x = (h ? q : s);
    float v = (l < LSEQ) ? x[((size_t)r * LSEQ + l) * DIM + d] : 0.f;
    g_Xh[idx] = __float2half(v);
}

// ---------------------------------------------------------------------------
// gemm: 128x128 block tile, 4 warps (2x2, warp tile 64x64), BK=64,
// double-buffered cp.async, SW128 smem rows (128B), 64KB smem -> 2 CTAs/SM.
// Per chunk stage {Ah, Bh} (32KB); per ks 8 ldsm + 32 HMMA.
// ---------------------------------------------------------------------------
#define SM_BUF 32768            // per buffer: Ah 16KB | Bh 16KB
#define SM_TOTAL 65536

__global__ void __launch_bounds__(128, 2) gemm_kernel() {
    extern __shared__ char smem[];
    uint32_t sb = s2u(smem);
    int tid = threadIdx.x, wid = tid >> 5, lane = tid & 31;
    int bx = blockIdx.x, by = blockIdx.y, h = blockIdx.z;

    const __half* Wh = g_Wh + ((size_t)h * MSTR + by * 128) * DIM;
    const __half* Xh = g_Xh + ((size_t)h * NSTR + bx * 128) * DIM;
    const __half* mats[2] = {Wh, Xh};

    int wm0 = (wid >> 1) * 64;          // warp m offset in tile
    int wn0 = (wid & 1) * 64;           // warp n offset in tile

    float acc[4][8][4];
#pragma unroll
    for (int mt = 0; mt < 4; mt++)
#pragma unroll
        for (int nt = 0; nt < 8; nt++)
#pragma unroll
            for (int i = 0; i < 4; i++) acc[mt][nt][i] = 0.f;

    // staging: 2 mats x 128 rows x 8 16B-chunks = 2048 cp16; 16 per thread
#define STAGE(cc)                                                              \
    {                                                                          \
        int koff = (cc) * 64;                                                  \
        uint32_t bb = sb + ((cc) & 1) * SM_BUF;                                \
        _Pragma("unroll")                                                      \
        for (int rep = 0; rep < 16; rep++) {                                   \
            int cid = rep * 128 + tid;                                         \
            int mat = cid >> 10;                                               \
            int r = (cid >> 3) & 127;                                          \
            int kc = cid & 7;                                                  \
            cp16(bb + mat * 16384 + SW128(r * 128 + kc * 16),                  \
                 mats[mat] + (size_t)r * DIM + koff + kc * 8);                 \
        }                                                                      \
        asm volatile("cp.async.commit_group;");                                \
    }

    STAGE(0);
    for (int c = 0; c < NCH; c++) {
        if (c + 1 < NCH) {
            STAGE(c + 1);
            asm volatile("cp.async.wait_group 1;");
        } else {
            asm volatile("cp.async.wait_group 0;");
        }
        __syncthreads();

        uint32_t sbAh = sb + (c & 1) * SM_BUF;
        uint32_t sbBh = sbAh + 16384;
#pragma unroll
        for (int ks = 0; ks < 4; ks++) {
            uint32_t ah[4][4], bh[4][4];
#pragma unroll
            for (int mt = 0; mt < 4; mt++) {
                int row = wm0 + mt * 16 + (lane & 15);
                int colh = lane >> 4;
                uint32_t off = SW128(row * 128 + (ks * 2 + colh) * 16);
                ldsm4(ah[mt], sbAh + off);
            }
#pragma unroll
            for (int bt = 0; bt < 4; bt++) {
                int n = wn0 + bt * 16 + ((lane >> 4) << 3) + (lane & 7);
                int khalf = (lane >> 3) & 1;
                uint32_t off = SW128(n * 128 + ks * 32 + khalf * 16);
                ldsm4(bh[bt], sbBh + off);
            }
#pragma unroll
            for (int mt = 0; mt < 4; mt++)
#pragma unroll
                for (int nt = 0; nt < 8; nt++)
                    mma_f16(acc[mt][nt], ah[mt], bh[nt >> 1] + (nt & 1) * 2);
        }
        __syncthreads();
    }
#undef STAGE

    // write accumulators to Z
    int gr = lane >> 2, gc = (lane & 3) * 2;
    float* Zp = g_Z + (size_t)h * MSTR * NSTR;
#pragma unroll
    for (int mt = 0; mt < 4; mt++) {
        int row0 = by * 128 + wm0 + mt * 16 + gr;
#pragma unroll
        for (int nt = 0; nt < 8; nt++) {
            int col = bx * 128 + wn0 + nt * 8 + gc;
            float2 lo = make_float2(acc[mt][nt][0], acc[mt][nt][1]);
            float2 hi = make_float2(acc[mt][nt][2], acc[mt][nt][3]);
            *(float2*)(Zp + (size_t)row0 * NSTR + col) = lo;
            *(float2*)(Zp + (size_t)(row0 + 8) * NSTR + col) = hi;
        }
    }
}

// ---------------------------------------------------------------------------
// epilogue: Y[h][r][conv*150+c][l] = sum_t Z[h][base+t*150+c][r*32 + l+t-pad]
// ---------------------------------------------------------------------------
template <int CONV>
__device__ __forceinline__ void epi_body(int r, int h) {
    const int k = CONV + 2;
    const int pad = (CONV >= 2) ? 2 : 1;
    const int base = (CONV == 0) ? 0 : (CONV == 1) ? 300 : (CONV == 2) ? 750 : 1350;
    const float* Zp = g_Z + (size_t)h * MSTR * NSTR + r * 32;
    float* out = (h ? g_B : g_A) + (size_t)r * NCC * LP + CONV * 150 * LP;
    for (int i = threadIdx.x; i < 150 * 32; i += 256) {
        int c = i >> 5, l = i & 31;
        float v = -1e30f;
        if (l < LSEQ) {
            v = 0.f;
#pragma unroll
            for (int t = 0; t < k; t++) {
                int lp = l + t - pad;
                if (lp >= 0 && lp < 32)
                    v += Zp[(size_t)(base + t * 150 + c) * NSTR + lp];
            }
        }
        out[c * LP + l] = v;
    }
}

__global__ void epilogue_kernel() {
    int r = blockIdx.x, h = blockIdx.z;
    switch (blockIdx.y) {
        case 0: epi_body<0>(r, h); break;
        case 1: epi_body<1>(r, h); break;
        case 2: epi_body<2>(r, h); break;
        case 3: epi_body<3>(r, h); break;
    }
}

// ---------------------------------------------------------------------------
// combine: 5x5 pair tiling. Block owns (b, 5 i's, 5 j's); stages 10 rows in
// cc-slabs of 60 through smem (stride-33 pad), serves 25 pairs per load.
// ---------------------------------------------------------------------------
#define CSLAB 60
#define CROWPAD 33
#define CROWSZ (CSLAB * CROWPAD)
#define CMB_SMEM (2 * 5 * CROWSZ * 4)    // 79200 bytes

__global__ void __launch_bounds__(256) combine_kernel(float* __restrict__ out) {
    extern __shared__ float cs[];
    float* sA = cs;
    float* sB = cs + 5 * CROWSZ;

    int blk = blockIdx.x;
    int b = blk / 25;
    int rem = blk - b * 25;
    int ig = rem / 5, jg = rem - (rem / 5) * 5;
    int b25 = b * 25;
    int tid = threadIdx.x;

    for (int s = 0; s < NCC / CSLAB; s++) {
        for (int idx = tid; idx < 5 * CSLAB * 8; idx += 256) {
            int row = idx / (CSLAB * 8);
            int rest = idx - row * (CSLAB * 8);
            int cc = rest >> 3, l4 = rest & 7;
            size_t goff = ((size_t)(b25 + ig * 5 + row) * NCC + s * CSLAB + cc) * LP
                        + l4 * 4;
            float4 va = *(const float4*)(g_A + goff);
            float* da = sA + row * CROWSZ + cc * CROWPAD + l4 * 4;
            da[0] = va.x; da[1] = va.y; da[2] = va.z; da[3] = va.w;
            size_t goffb = ((size_t)(b25 + jg * 5 + row) * NCC + s * CSLAB + cc) * LP
                         + l4 * 4;
            float4 vb = *(const float4*)(g_B + goffb);
            float* db = sB + row * CROWSZ + cc * CROWPAD + l4 * 4;
            db[0] = vb.x; db[1] = vb.y; db[2] = vb.z; db[3] = vb.w;
        }
        __syncthreads();

        for (int o = tid; o < 25 * CSLAB; o += 256) {
            int pair = o / CSLAB;
            int cci = o - pair * CSLAB;
            int ii = pair / 5, jj = pair - ii * 5;
            const float* ar = sA + ii * CROWSZ + cci * CROWPAD;
            const float* br = sB + jj * CROWSZ + cci * CROWPAD;
            float m = -3.0e38f;
#pragma unroll
            for (int l = 0; l < 32; l++)
                m = fmaxf(m, ar[l] + br[l]);
            int cc = s * CSLAB + cci;
            m = fmaxf(0.f, m + g_bias[cc]);
            int p = b * 625 + (ig * 5 + ii) * 25 + (jg * 5 + jj);
            int conv = cc / 150;
            int c = cc - conv * 150;
            if (c < 75)
                out[p * 300 + conv * 75 + c] = m;
            else
                out[750000 + p * 300 + conv * 75 + (c - 75)] = m;
        }
        __syncthreads();
    }
}

// ---------------------------------------------------------------------------
extern "C" void kernel_launch(void* const* d_in, const int* in_sizes, int n_in,
                              void* d_out, int out_size) {
    const float* s  = (const float*)d_in[0];
    const float* q  = (const float*)d_in[1];
    const float* w2 = (const float*)d_in[2];
    const float* b2 = (const float*)d_in[3];
    const float* w3 = (const float*)d_in[4];
    const float* b3 = (const float*)d_in[5];
    const float* w4 = (const float*)d_in[6];
    const float* b4 = (const float*)d_in[7];
    const float* w5 = (const float*)d_in[8];
    const float* b5 = (const float*)d_in[9];
    float* out = (float*)d_out;

    cudaFuncSetAttribute(gemm_kernel, cudaFuncAttributeMaxDynamicSharedMemorySize,
                         SM_TOTAL);
    cudaFuncSetAttribute(combine_kernel, cudaFuncAttributeMaxDynamicSharedMemorySize,
                         CMB_SMEM);

    wsplit_kernel<<<(2 * MSTR * DIM + 255) / 256, 256>>>(w2, b2, w3, b3, w4, b4, w5, b5);
    xsplit_kernel<<<(2 * NSTR * DIM + 255) / 256, 256>>>(s, q);
    gemm_kernel<<<dim3(NSTR / 128, MSTR / 128, 2), 128, SM_TOTAL>>>();
    epilogue_kernel<<<dim3(NROWS, 4, 2), 256>>>();
    combine_kernel<<<100, 256, CMB_SMEM>>>(out);
}

// round 11
// speedup vs baseline: 6.1745x; 1.0464x over previous
#include <cuda_runtime.h>
#include <cuda_fp16.h>
#include <cstdint>

// ---------------------------------------------------------------------------
// CNNInteractLayer — mma.sync fp16 GEMM-factored implementation.
// conv(concat(s_i,q_j)) = conv_s(s_i) + conv_q(q_j) + bias  (conv is linear).
// Per half: Z[2176x3200] = W[2176x512] @ X[512x3200]^T-view on tensor cores,
// single-product fp16 (quantization ~2^-12 relative, measured ~1.4e-4 << 1e-3
// gate), fp32 accumulation.
// Then shift-add epilogue + 5x5-tiled pairwise combine.
// ---------------------------------------------------------------------------

#define LSEQ 31
#define DIM 512
#define NROWS 100
#define NCC 600
#define LP 32
#define MTOT 2100
#define MSTR 2176          // 17 * 128
#define NSTR 3200          // 100 rows * 32 = 25 * 128
#define NCH 8              // 512 / 64 k-chunks

typedef unsigned long long ull;

__device__ __half g_Wh[2 * MSTR * DIM];            // [half][m][k]
__device__ __half g_Xh[2 * NSTR * DIM];            // [half][n][k]
__device__ float g_Z[2 * (size_t)MSTR * NSTR];
__device__ float g_bias[NCC];
__device__ float g_A[NROWS * NCC * LP];
__device__ float g_B[NROWS * NCC * LP];

// ---------------- PTX helpers ----------------
__device__ __forceinline__ uint32_t s2u(const void* p) {
    uint32_t a;
    asm("{ .reg .u64 t; cvta.to.shared.u64 t, %1; cvt.u32.u64 %0, t; }"
        : "=r"(a) : "l"(p));
    return a;
}
__device__ __forceinline__ void cp16(uint32_t saddr, const void* gptr) {
    asm volatile("cp.async.cg.shared.global [%0], [%1], 16;"
                 :: "r"(saddr), "l"(gptr));
}
__device__ __forceinline__ void ldsm4(uint32_t* r, uint32_t addr) {
    asm volatile("ldmatrix.sync.aligned.m8n8.x4.shared.b16 {%0,%1,%2,%3}, [%4];"
                 : "=r"(r[0]), "=r"(r[1]), "=r"(r[2]), "=r"(r[3]) : "r"(addr));
}
__device__ __forceinline__ void mma_f16(float* d, const uint32_t* a,
                                        const uint32_t* b) {
    asm volatile(
        "mma.sync.aligned.m16n8k16.row.col.f32.f16.f16.f32 "
        "{%0,%1,%2,%3}, {%4,%5,%6,%7}, {%8,%9}, {%0,%1,%2,%3};"
        : "+f"(d[0]), "+f"(d[1]), "+f"(d[2]), "+f"(d[3])
        : "r"(a[0]), "r"(a[1]), "r"(a[2]), "r"(a[3]), "r"(b[0]), "r"(b[1]));
}
#define SW128(x) ((x) ^ (((x) >> 3) & 0x70))

// ---------------------------------------------------------------------------
// prep: ONE kernel for W gather->fp16, X transpose->fp16, and bias.
// W: w_k (150,1024,k) -> Wh[h][m=base+t*150+c][d];  X: [h][n=r*32+l][d].
// ---------------------------------------------------------------------------
#define NWELEM (2 * MSTR * DIM)          // 2228224
#define NXELEM (2 * NSTR * DIM)          // 3276800

__global__ void prep_kernel(const float* __restrict__ s, const float* __restrict__ q,
                            const float* __restrict__ w2, const float* __restrict__ b2,
                            const float* __restrict__ w3, const float* __restrict__ b3,
                            const float* __restrict__ w4, const float* __restrict__ b4,
                            const float* __restrict__ w5, const float* __restrict__ b5) {
    int idx = blockIdx.x * blockDim.x + threadIdx.x;
    if (idx < NCC) {
        int conv = idx / 150, c = idx - conv * 150;
        const float* bp = (conv == 0) ? b2 : (conv == 1) ? b3 : (conv == 2) ? b4 : b5;
        g_bias[idx] = bp[c];
    }
    if (idx < NWELEM) {
        int h = idx / (MSTR * DIM);
        int rem = idx - h * (MSTR * DIM);
        int m = rem / DIM;
        int d = rem - m * DIM;
        float v = 0.f;
        if (m < MTOT) {
            int conv = (m < 300) ? 0 : (m < 750) ? 1 : (m < 1350) ? 2 : 3;
            int base = (conv == 0) ? 0 : (conv == 1) ? 300 : (conv == 2) ? 750 : 1350;
            int k = conv + 2;
            int mm = m - base;
            int t = mm / 150, c = mm - t * 150;
            const float* w = (conv == 0) ? w2 : (conv == 1) ? w3 : (conv == 2) ? w4 : w5;
            v = w[(c * 1024 + h * DIM + d) * k + t];
        }
        g_Wh[idx] = __float2half(v);
    }
    if (idx < NXELEM) {
        int h = idx / (NSTR * DIM);
        int rem = idx - h * (NSTR * DIM);
        int n = rem / DIM;
        int d = rem - n * DIM;
        int r = n >> 5, l = n & 31;
        const float* x = (h ? q : s);
        float v = (l < LSEQ) ? x[((size_t)r * LSEQ + l) * DIM + d] : 0.f;
        g_Xh[idx] = __float2half(v);
    }
}

// ---------------------------------------------------------------------------
// gemm: 128x128 block tile, 4 warps (2x2, warp tile 64x64), BK=64,
// double-buffered cp.async, SW128 smem rows (128B), 64KB smem -> 2 CTAs/SM.
// ---------------------------------------------------------------------------
#define SM_BUF 32768            // per buffer: Ah 16KB | Bh 16KB
#define SM_TOTAL 65536

__global__ void __launch_bounds__(128, 2) gemm_kernel() {
    extern __shared__ char smem[];
    uint32_t sb = s2u(smem);
    int tid = threadIdx.x, wid = tid >> 5, lane = tid & 31;
    int bx = blockIdx.x, by = blockIdx.y, h = blockIdx.z;

    const __half* Wh = g_Wh + ((size_t)h * MSTR + by * 128) * DIM;
    const __half* Xh = g_Xh + ((size_t)h * NSTR + bx * 128) * DIM;
    const __half* mats[2] = {Wh, Xh};

    int wm0 = (wid >> 1) * 64;
    int wn0 = (wid & 1) * 64;

    float acc[4][8][4];
#pragma unroll
    for (int mt = 0; mt < 4; mt++)
#pragma unroll
        for (int nt = 0; nt < 8; nt++)
#pragma unroll
            for (int i = 0; i < 4; i++) acc[mt][nt][i] = 0.f;

#define STAGE(cc)                                                              \
    {                                                                          \
        int koff = (cc) * 64;                                                  \
        uint32_t bb = sb + ((cc) & 1) * SM_BUF;                                \
        _Pragma("unroll")                                                      \
        for (int rep = 0; rep < 16; rep++) {                                   \
            int cid = rep * 128 + tid;                                         \
            int mat = cid >> 10;                                               \
            int r = (cid >> 3) & 127;                                          \
            int kc = cid & 7;                                                  \
            cp16(bb + mat * 16384 + SW128(r * 128 + kc * 16),                  \
                 mats[mat] + (size_t)r * DIM + koff + kc * 8);                 \
        }                                                                      \
        asm volatile("cp.async.commit_group;");                                \
    }

    STAGE(0);
    for (int c = 0; c < NCH; c++) {
        if (c + 1 < NCH) {
            STAGE(c + 1);
            asm volatile("cp.async.wait_group 1;");
        } else {
            asm volatile("cp.async.wait_group 0;");
        }
        __syncthreads();

        uint32_t sbAh = sb + (c & 1) * SM_BUF;
        uint32_t sbBh = sbAh + 16384;
#pragma unroll
        for (int ks = 0; ks < 4; ks++) {
            uint32_t ah[4][4], bh[4][4];
#pragma unroll
            for (int mt = 0; mt < 4; mt++) {
                int row = wm0 + mt * 16 + (lane & 15);
                int colh = lane >> 4;
                uint32_t off = SW128(row * 128 + (ks * 2 + colh) * 16);
                ldsm4(ah[mt], sbAh + off);
            }
#pragma unroll
            for (int bt = 0; bt < 4; bt++) {
                int n = wn0 + bt * 16 + ((lane >> 4) << 3) + (lane & 7);
                int khalf = (lane >> 3) & 1;
                uint32_t off = SW128(n * 128 + ks * 32 + khalf * 16);
                ldsm4(bh[bt], sbBh + off);
            }
#pragma unroll
            for (int mt = 0; mt < 4; mt++)
#pragma unroll
                for (int nt = 0; nt < 8; nt++)
                    mma_f16(acc[mt][nt], ah[mt], bh[nt >> 1] + (nt & 1) * 2);
        }
        __syncthreads();
    }
#undef STAGE

    int gr = lane >> 2, gc = (lane & 3) * 2;
    float* Zp = g_Z + (size_t)h * MSTR * NSTR;
#pragma unroll
    for (int mt = 0; mt < 4; mt++) {
        int row0 = by * 128 + wm0 + mt * 16 + gr;
#pragma unroll
        for (int nt = 0; nt < 8; nt++) {
            int col = bx * 128 + wn0 + nt * 8 + gc;
            float2 lo = make_float2(acc[mt][nt][0], acc[mt][nt][1]);
            float2 hi = make_float2(acc[mt][nt][2], acc[mt][nt][3]);
            *(float2*)(Zp + (size_t)row0 * NSTR + col) = lo;
            *(float2*)(Zp + (size_t)(row0 + 8) * NSTR + col) = hi;
        }
    }
}

// ---------------------------------------------------------------------------
// epilogue: Y[h][r][conv*150+c][l] = sum_t Z[h][base+t*150+c][r*32 + l+t-pad]
// 2-row ILP per thread (c and c+75): two independent load chains.
// ---------------------------------------------------------------------------
template <int CONV>
__device__ __forceinline__ void epi_body(int r, int h) {
    const int k = CONV + 2;
    const int pad = (CONV >= 2) ? 2 : 1;
    const int base = (CONV == 0) ? 0 : (CONV == 1) ? 300 : (CONV == 2) ? 750 : 1350;
    const float* Zp = g_Z + (size_t)h * MSTR * NSTR + r * 32;
    float* out = (h ? g_B : g_A) + (size_t)r * NCC * LP + CONV * 150 * LP;
    for (int i = threadIdx.x; i < 75 * 32; i += 256) {
        int c = i >> 5, l = i & 31;             // c in 0..74
        float v0 = -1e30f, v1 = -1e30f;
        if (l < LSEQ) {
            v0 = 0.f; v1 = 0.f;
#pragma unroll
            for (int t = 0; t < k; t++) {
                int lp = l + t - pad;
                if (lp >= 0 && lp < 32) {
                    v0 += __ldg(Zp + (size_t)(base + t * 150 + c) * NSTR + lp);
                    v1 += __ldg(Zp + (size_t)(base + t * 150 + c + 75) * NSTR + lp);
                }
            }
        }
        out[c * LP + l] = v0;
        out[(c + 75) * LP + l] = v1;
    }
}

__global__ void epilogue_kernel() {
    int r = blockIdx.x, h = blockIdx.z;
    switch (blockIdx.y) {
        case 0: epi_body<0>(r, h); break;
        case 1: epi_body<1>(r, h); break;
        case 2: epi_body<2>(r, h); break;
        case 3: epi_body<3>(r, h); break;
    }
}

// ---------------------------------------------------------------------------
// combine: 5x5 pair tiling. Block owns (b, 5 i's, 5 j's); stages 10 rows in
// cc-slabs of 60 through smem (stride-33 pad), serves 25 pairs per load.
// ---------------------------------------------------------------------------
#define CSLAB 60
#define CROWPAD 33
#define CROWSZ (CSLAB * CROWPAD)
#define CMB_SMEM (2 * 5 * CROWSZ * 4)    // 79200 bytes

__global__ void __launch_bounds__(256) combine_kernel(float* __restrict__ out) {
    extern __shared__ float cs[];
    float* sA = cs;
    float* sB = cs + 5 * CROWSZ;

    int blk = blockIdx.x;
    int b = blk / 25;
    int rem = blk - b * 25;
    int ig = rem / 5, jg = rem - (rem / 5) * 5;
    int b25 = b * 25;
    int tid = threadIdx.x;

    for (int s = 0; s < NCC / CSLAB; s++) {
        for (int idx = tid; idx < 5 * CSLAB * 8; idx += 256) {
            int row = idx / (CSLAB * 8);
            int rest = idx - row * (CSLAB * 8);
            int cc = rest >> 3, l4 = rest & 7;
            size_t goff = ((size_t)(b25 + ig * 5 + row) * NCC + s * CSLAB + cc) * LP
                        + l4 * 4;
            float4 va = *(const float4*)(g_A + goff);
            float* da = sA + row * CROWSZ + cc * CROWPAD + l4 * 4;
            da[0] = va.x; da[1] = va.y; da[2] = va.z; da[3] = va.w;
            size_t goffb = ((size_t)(b25 + jg * 5 + row) * NCC + s * CSLAB + cc) * LP
                         + l4 * 4;
            float4 vb = *(const float4*)(g_B + goffb);
            float* db = sB + row * CROWSZ + cc * CROWPAD + l4 * 4;
            db[0] = vb.x; db[1] = vb.y; db[2] = vb.z; db[3] = vb.w;
        }
        __syncthreads();

        for (int o = tid; o < 25 * CSLAB; o += 256) {
            int pair = o / CSLAB;
            int cci = o - pair * CSLAB;
            int ii = pair / 5, jj = pair - ii * 5;
            const float* ar = sA + ii * CROWSZ + cci * CROWPAD;
            const float* br = sB + jj * CROWSZ + cci * CROWPAD;
            float m = -3.0e38f;
#pragma unroll
            for (int l = 0; l < 32; l++)
                m = fmaxf(m, ar[l] + br[l]);
            int cc = s * CSLAB + cci;
            m = fmaxf(0.f, m + g_bias[cc]);
            int p = b * 625 + (ig * 5 + ii) * 25 + (jg * 5 + jj);
            int conv = cc / 150;
            int c = cc - conv * 150;
            if (c < 75)
                out[p * 300 + conv * 75 + c] = m;
            else
                out[750000 + p * 300 + conv * 75 + (c - 75)] = m;
        }
        __syncthreads();
    }
}

// ---------------------------------------------------------------------------
extern "C" void kernel_launch(void* const* d_in, const int* in_sizes, int n_in,
                              void* d_out, int out_size) {
    const float* s  = (const float*)d_in[0];
    const float* q  = (const float*)d_in[1];
    const float* w2 = (const float*)d_in[2];
    const float* b2 = (const float*)d_in[3];
    const float* w3 = (const float*)d_in[4];
    const float* b3 = (const float*)d_in[5];
    const float* w4 = (const float*)d_in[6];
    const float* b4 = (const float*)d_in[7];
    const float* w5 = (const float*)d_in[8];
    const float* b5 = (const float*)d_in[9];
    float* out = (float*)d_out;

    cudaFuncSetAttribute(gemm_kernel, cudaFuncAttributeMaxDynamicSharedMemorySize,
                         SM_TOTAL);
    cudaFuncSetAttribute(combine_kernel, cudaFuncAttributeMaxDynamicSharedMemorySize,
                         CMB_SMEM);

    prep_kernel<<<(NXELEM + 255) / 256, 256>>>(s, q, w2, b2, w3, b3, w4, b4, w5, b5);
    gemm_kernel<<<dim3(NSTR / 128, MSTR / 128, 2), 128, SM_TOTAL>>>();
    epilogue_kernel<<<dim3(NROWS, 4, 2), 256>>>();
    combine_kernel<<<100, 256, CMB_SMEM>>>(out);
}

// round 13
// speedup vs baseline: 7.9107x; 1.2812x over previous
#include <cuda_runtime.h>
#include <cuda_fp16.h>
#include <cstdint>

// ---------------------------------------------------------------------------
// CNNInteractLayer — mma.sync fp16 GEMM-factored implementation.
// conv(concat(s_i,q_j)) = conv_s(s_i) + conv_q(q_j) + bias  (conv is linear).
// Per half: Z[2176x3200] = W[2176x512] @ X[512x3200]^T-view on tensor cores,
// single-product fp16 (quantization ~2^-12 relative, measured ~1.4e-4 << 1e-3
// gate), fp32 accumulation.
// Then shift-add epilogue + grid-parallel 5x5-tiled pairwise combine.
// ---------------------------------------------------------------------------

#define LSEQ 31
#define DIM 512
#define NROWS 100
#define NCC 600
#define LP 32
#define MTOT 2100
#define MSTR 2176          // 17 * 128
#define NSTR 3200          // 100 rows * 32 = 25 * 128
#define NCH 8              // 512 / 64 k-chunks

typedef unsigned long long ull;

__device__ __half g_Wh[2 * MSTR * DIM];            // [half][m][k]
__device__ __half g_Xh[2 * NSTR * DIM];            // [half][n][k]
__device__ float g_Z[2 * (size_t)MSTR * NSTR];
__device__ float g_bias[NCC];
__device__ float g_A[NROWS * NCC * LP];
__device__ float g_B[NROWS * NCC * LP];

// ---------------- PTX helpers ----------------
__device__ __forceinline__ uint32_t s2u(const void* p) {
    uint32_t a;
    asm("{ .reg .u64 t; cvta.to.shared.u64 t, %1; cvt.u32.u64 %0, t; }"
        : "=r"(a) : "l"(p));
    return a;
}
__device__ __forceinline__ void cp16(uint32_t saddr, const void* gptr) {
    asm volatile("cp.async.cg.shared.global [%0], [%1], 16;"
                 :: "r"(saddr), "l"(gptr));
}
__device__ __forceinline__ void ldsm4(uint32_t* r, uint32_t addr) {
    asm volatile("ldmatrix.sync.aligned.m8n8.x4.shared.b16 {%0,%1,%2,%3}, [%4];"
                 : "=r"(r[0]), "=r"(r[1]), "=r"(r[2]), "=r"(r[3]) : "r"(addr));
}
__device__ __forceinline__ void mma_f16(float* d, const uint32_t* a,
                                        const uint32_t* b) {
    asm volatile(
        "mma.sync.aligned.m16n8k16.row.col.f32.f16.f16.f32 "
        "{%0,%1,%2,%3}, {%4,%5,%6,%7}, {%8,%9}, {%0,%1,%2,%3};"
        : "+f"(d[0]), "+f"(d[1]), "+f"(d[2]), "+f"(d[3])
        : "r"(a[0]), "r"(a[1]), "r"(a[2]), "r"(a[3]), "r"(b[0]), "r"(b[1]));
}
#define SW128(x) ((x) ^ (((x) >> 3) & 0x70))

// ---------------------------------------------------------------------------
// prep: ONE kernel for W gather->fp16, X transpose->fp16, and bias.
// ---------------------------------------------------------------------------
#define NWELEM (2 * MSTR * DIM)
#define NXELEM (2 * NSTR * DIM)

__global__ void prep_kernel(const float* __restrict__ s, const float* __restrict__ q,
                            const float* __restrict__ w2, const float* __restrict__ b2,
                            const float* __restrict__ w3, const float* __restrict__ b3,
                            const float* __restrict__ w4, const float* __restrict__ b4,
                            const float* __restrict__ w5, const float* __restrict__ b5) {
    int idx = blockIdx.x * blockDim.x + threadIdx.x;
    if (idx < NCC) {
        int conv = idx / 150, c = idx - conv * 150;
        const float* bp = (conv == 0) ? b2 : (conv == 1) ? b3 : (conv == 2) ? b4 : b5;
        g_bias[idx] = bp[c];
    }
    if (idx < NWELEM) {
        int h = idx / (MSTR * DIM);
        int rem = idx - h * (MSTR * DIM);
        int m = rem / DIM;
        int d = rem - m * DIM;
        float v = 0.f;
        if (m < MTOT) {
            int conv = (m < 300) ? 0 : (m < 750) ? 1 : (m < 1350) ? 2 : 3;
            int base = (conv == 0) ? 0 : (conv == 1) ? 300 : (conv == 2) ? 750 : 1350;
            int k = conv + 2;
            int mm = m - base;
            int t = mm / 150, c = mm - t * 150;
            const float* w = (conv == 0) ? w2 : (conv == 1) ? w3 : (conv == 2) ? w4 : w5;
            v = w[(c * 1024 + h * DIM + d) * k + t];
        }
        g_Wh[idx] = __float2half(v);
    }
    if (idx < NXELEM) {
        int h = idx / (NSTR * DIM);
        int rem = idx - h * (NSTR * DIM);
        int n = rem / DIM;
        int d = rem - n * DIM;
        int r = n >> 5, l = n & 31;
        const float* x = (h ? q : s);
        float v = (l < LSEQ) ? x[((size_t)r * LSEQ + l) * DIM + d] : 0.f;
        g_Xh[idx] = __float2half(v);
    }
}

// ---------------------------------------------------------------------------
// gemm: 128x128 block tile, 4 warps (2x2, warp tile 64x64), BK=64,
// double-buffered cp.async, SW128 smem rows (128B), 64KB smem -> 2 CTAs/SM.
// ---------------------------------------------------------------------------
#define SM_BUF 32768
#define SM_TOTAL 65536

__global__ void __launch_bounds__(128, 2) gemm_kernel() {
    extern __shared__ char smem[];
    uint32_t sb = s2u(smem);
    int tid = threadIdx.x, wid = tid >> 5, lane = tid & 31;
    int bx = blockIdx.x, by = blockIdx.y, h = blockIdx.z;

    const __half* Wh = g_Wh + ((size_t)h * MSTR + by * 128) * DIM;
    const __half* Xh = g_Xh + ((size_t)h * NSTR + bx * 128) * DIM;
    const __half* mats[2] = {Wh, Xh};

    int wm0 = (wid >> 1) * 64;
    int wn0 = (wid & 1) * 64;

    float acc[4][8][4];
#pragma unroll
    for (int mt = 0; mt < 4; mt++)
#pragma unroll
        for (int nt = 0; nt < 8; nt++)
#pragma unroll
            for (int i = 0; i < 4; i++) acc[mt][nt][i] = 0.f;

#define STAGE(cc)                                                              \
    {                                                                          \
        int koff = (cc) * 64;                                                  \
        uint32_t bb = sb + ((cc) & 1) * SM_BUF;                                \
        _Pragma("unroll")                                                      \
        for (int rep = 0; rep < 16; rep++) {                                   \
            int cid = rep * 128 + tid;                                         \
            int mat = cid >> 10;                                               \
            int r = (cid >> 3) & 127;                                          \
            int kc = cid & 7;                                                  \
            cp16(bb + mat * 16384 + SW128(r * 128 + kc * 16),                  \
                 mats[mat] + (size_t)r * DIM + koff + kc * 8);                 \
        }                                                                      \
        asm volatile("cp.async.commit_group;");                                \
    }

    STAGE(0);
    for (int c = 0; c < NCH; c++) {
        if (c + 1 < NCH) {
            STAGE(c + 1);
            asm volatile("cp.async.wait_group 1;");
        } else {
            asm volatile("cp.async.wait_group 0;");
        }
        __syncthreads();

        uint32_t sbAh = sb + (c & 1) * SM_BUF;
        uint32_t sbBh = sbAh + 16384;
#pragma unroll
        for (int ks = 0; ks < 4; ks++) {
            uint32_t ah[4][4], bh[4][4];
#pragma unroll
            for (int mt = 0; mt < 4; mt++) {
                int row = wm0 + mt * 16 + (lane & 15);
                int colh = lane >> 4;
                uint32_t off = SW128(row * 128 + (ks * 2 + colh) * 16);
                ldsm4(ah[mt], sbAh + off);
            }
#pragma unroll
            for (int bt = 0; bt < 4; bt++) {
                int n = wn0 + bt * 16 + ((lane >> 4) << 3) + (lane & 7);
                int khalf = (lane >> 3) & 1;
                uint32_t off = SW128(n * 128 + ks * 32 + khalf * 16);
                ldsm4(bh[bt], sbBh + off);
            }
#pragma unroll
            for (int mt = 0; mt < 4; mt++)
#pragma unroll
                for (int nt = 0; nt < 8; nt++)
                    mma_f16(acc[mt][nt], ah[mt], bh[nt >> 1] + (nt & 1) * 2);
        }
        __syncthreads();
    }
#undef STAGE

    int gr = lane >> 2, gc = (lane & 3) * 2;
    float* Zp = g_Z + (size_t)h * MSTR * NSTR;
#pragma unroll
    for (int mt = 0; mt < 4; mt++) {
        int row0 = by * 128 + wm0 + mt * 16 + gr;
#pragma unroll
        for (int nt = 0; nt < 8; nt++) {
            int col = bx * 128 + wn0 + nt * 8 + gc;
            float2 lo = make_float2(acc[mt][nt][0], acc[mt][nt][1]);
            float2 hi = make_float2(acc[mt][nt][2], acc[mt][nt][3]);
            *(float2*)(Zp + (size_t)row0 * NSTR + col) = lo;
            *(float2*)(Zp + (size_t)(row0 + 8) * NSTR + col) = hi;
        }
    }
}

// ---------------------------------------------------------------------------
// epilogue: Y[h][r][conv*150+c][l] = sum_t Z[h][base+t*150+c][r*32 + l+t-pad]
// 2-row ILP per thread (c and c+75).
// ---------------------------------------------------------------------------
template <int CONV>
__device__ __forceinline__ void epi_body(int r, int h) {
    const int k = CONV + 2;
    const int pad = (CONV >= 2) ? 2 : 1;
    const int base = (CONV == 0) ? 0 : (CONV == 1) ? 300 : (CONV == 2) ? 750 : 1350;
    const float* Zp = g_Z + (size_t)h * MSTR * NSTR + r * 32;
    float* out = (h ? g_B : g_A) + (size_t)r * NCC * LP + CONV * 150 * LP;
    for (int i = threadIdx.x; i < 75 * 32; i += 256) {
        int c = i >> 5, l = i & 31;
        float v0 = -1e30f, v1 = -1e30f;
        if (l < LSEQ) {
            v0 = 0.f; v1 = 0.f;
#pragma unroll
            for (int t = 0; t < k; t++) {
                int lp = l + t - pad;
                if (lp >= 0 && lp < 32) {
                    v0 += __ldg(Zp + (size_t)(base + t * 150 + c) * NSTR + lp);
                    v1 += __ldg(Zp + (size_t)(base + t * 150 + c + 75) * NSTR + lp);
                }
            }
        }
        out[c * LP + l] = v0;
        out[(c + 75) * LP + l] = v1;
    }
}

__global__ void epilogue_kernel() {
    int r = blockIdx.x, h = blockIdx.z;
    switch (blockIdx.y) {
        case 0: epi_body<0>(r, h); break;
        case 1: epi_body<1>(r, h); break;
        case 2: epi_body<2>(r, h); break;
        case 3: epi_body<3>(r, h); break;
    }
}

// ---------------------------------------------------------------------------
// combine: grid-parallel 5x5 pair tiling. Block = (pair-tile, cc-slab of 40).
// Stages 10 rows (stride-36 pad -> float4 LDS, conflict-free), computes 25x40
// outputs, exits. out_ch = max(0, max_l(A+B) + bias).
// ---------------------------------------------------------------------------
#define CSLAB 40
#define NSLAB (NCC / CSLAB)              // 15
#define CROWPAD 36                       // 16B-aligned, 36 % 32 == 4
#define CROWSZ (CSLAB * CROWPAD)         // 1440 floats per staged row
#define CMB_SMEM (2 * 5 * CROWSZ * 4)    // 57600 bytes

__global__ void __launch_bounds__(256) combine_kernel(float* __restrict__ out) {
    extern __shared__ float cs[];
    float* sA = cs;                      // [5][CROWSZ]
    float* sB = cs + 5 * CROWSZ;

    int blk = blockIdx.x;                // 0..99 pair tile
    int sl = blockIdx.y;                 // 0..14 cc slab
    int b = blk / 25;
    int rem = blk - b * 25;
    int ig = rem / 5, jg = rem - (rem / 5) * 5;
    int b25 = b * 25;
    int tid = threadIdx.x;

    // stage 5 A rows + 5 B rows for this slab (float4 both sides)
    for (int idx = tid; idx < 10 * CSLAB * 8; idx += 256) {
        int row = idx / (CSLAB * 8);     // 0..9 (0-4: A, 5-9: B)
        int rest = idx - row * (CSLAB * 8);
        int cc = rest >> 3, l4 = rest & 7;
        int isB = row >= 5;
        int rloc = isB ? row - 5 : row;
        const float* gsrc = isB ? g_B : g_A;
        int grow = b25 + (isB ? jg : ig) * 5 + rloc;
        float4 v = *(const float4*)(gsrc + ((size_t)grow * NCC + sl * CSLAB + cc) * LP
                                    + l4 * 4);
        float* d = (isB ? sB : sA) + rloc * CROWSZ + cc * CROWPAD + l4 * 4;
        *(float4*)d = v;
    }
    __syncthreads();

    for (int o = tid; o < 25 * CSLAB; o += 256) {
        int pair = o / CSLAB;
        int cci = o - pair * CSLAB;
        int ii = pair / 5, jj = pair - ii * 5;
        const float4* ar = (const float4*)(sA + ii * CROWSZ + cci * CROWPAD);
        const float4* br = (const float4*)(sB + jj * CROWSZ + cci * CROWPAD);
        float m = -3.0e38f;
#pragma unroll
        for (int l4 = 0; l4 < 8; l4++) {
            float4 a = ar[l4];
            float4 bb = br[l4];
            m = fmaxf(m, a.x + bb.x);
            m = fmaxf(m, a.y + bb.y);
            m = fmaxf(m, a.z + bb.z);
            m = fmaxf(m, a.w + bb.w);
        }
        int cc = sl * CSLAB + cci;
        m = fmaxf(0.f, m + g_bias[cc]);
        int p = b * 625 + (ig * 5 + ii) * 25 + (jg * 5 + jj);
        int conv = cc / 150;
        int c = cc - conv * 150;
        if (c < 75)
            out[p * 300 + conv * 75 + c] = m;
        else
            out[750000 + p * 300 + conv * 75 + (c - 75)] = m;
    }
}

// ---------------------------------------------------------------------------
extern "C" void kernel_launch(void* const* d_in, const int* in_sizes, int n_in,
                              void* d_out, int out_size) {
    const float* s  = (const float*)d_in[0];
    const float* q  = (const float*)d_in[1];
    const float* w2 = (const float*)d_in[2];
    const float* b2 = (const float*)d_in[3];
    const float* w3 = (const float*)d_in[4];
    const float* b3 = (const float*)d_in[5];
    const float* w4 = (const float*)d_in[6];
    const float* b4 = (const float*)d_in[7];
    const float* w5 = (const float*)d_in[8];
    const float* b5 = (const float*)d_in[9];
    float* out = (float*)d_out;

    cudaFuncSetAttribute(gemm_kernel, cudaFuncAttributeMaxDynamicSharedMemorySize,
                         SM_TOTAL);
    cudaFuncSetAttribute(combine_kernel, cudaFuncAttributeMaxDynamicSharedMemorySize,
                         CMB_SMEM);

    prep_kernel<<<(NXELEM + 255) / 256, 256>>>(s, q, w2, b2, w3, b3, w4, b4, w5, b5);
    gemm_kernel<<<dim3(NSTR / 128, MSTR / 128, 2), 128, SM_TOTAL>>>();
    epilogue_kernel<<<dim3(NROWS, 4, 2), 256>>>();
    combine_kernel<<<dim3(100, NSLAB), 256, CMB_SMEM>>>(out);
}

// round 14
// speedup vs baseline: 8.3613x; 1.0570x over previous
#include <cuda_runtime.h>
#include <cuda_fp16.h>
#include <cstdint>

// ---------------------------------------------------------------------------
// CNNInteractLayer — mma.sync fp16 GEMM-factored implementation.
// conv(concat(s_i,q_j)) = conv_s(s_i) + conv_q(q_j) + bias  (conv is linear).
// Per half: Z[2176x3200] = W[2176x512] @ X[512x3200]^T-view on tensor cores,
// single-product fp16 (quantization ~1.4e-4 << 1e-3 gate), fp32 accumulation.
// Then shift-add epilogue + register-tiled pairwise combine.
// ---------------------------------------------------------------------------

#define LSEQ 31
#define DIM 512
#define NROWS 100
#define NCC 600
#define LP 32
#define MTOT 2100
#define MSTR 2176          // 17 * 128
#define NSTR 3200          // 100 rows * 32 = 25 * 128
#define NCH 8              // 512 / 64 k-chunks

typedef unsigned long long ull;

__device__ __half g_Wh[2 * MSTR * DIM];            // [half][m][k]
__device__ __half g_Xh[2 * NSTR * DIM];            // [half][n][k]
__device__ float g_Z[2 * (size_t)MSTR * NSTR];
__device__ float g_bias[NCC];
__device__ float g_A[NROWS * NCC * LP];
__device__ float g_B[NROWS * NCC * LP];

// ---------------- PTX helpers ----------------
__device__ __forceinline__ uint32_t s2u(const void* p) {
    uint32_t a;
    asm("{ .reg .u64 t; cvta.to.shared.u64 t, %1; cvt.u32.u64 %0, t; }"
        : "=r"(a) : "l"(p));
    return a;
}
__device__ __forceinline__ void cp16(uint32_t saddr, const void* gptr) {
    asm volatile("cp.async.cg.shared.global [%0], [%1], 16;"
                 :: "r"(saddr), "l"(gptr));
}
__device__ __forceinline__ void ldsm4(uint32_t* r, uint32_t addr) {
    asm volatile("ldmatrix.sync.aligned.m8n8.x4.shared.b16 {%0,%1,%2,%3}, [%4];"
                 : "=r"(r[0]), "=r"(r[1]), "=r"(r[2]), "=r"(r[3]) : "r"(addr));
}
__device__ __forceinline__ void mma_f16(float* d, const uint32_t* a,
                                        const uint32_t* b) {
    asm volatile(
        "mma.sync.aligned.m16n8k16.row.col.f32.f16.f16.f32 "
        "{%0,%1,%2,%3}, {%4,%5,%6,%7}, {%8,%9}, {%0,%1,%2,%3};"
        : "+f"(d[0]), "+f"(d[1]), "+f"(d[2]), "+f"(d[3])
        : "r"(a[0]), "r"(a[1]), "r"(a[2]), "r"(a[3]), "r"(b[0]), "r"(b[1]));
}
#define SW128(x) ((x) ^ (((x) >> 3) & 0x70))

// ---------------------------------------------------------------------------
// prep: ONE kernel for W gather->fp16, X transpose->fp16, and bias.
// ---------------------------------------------------------------------------
#define NWELEM (2 * MSTR * DIM)
#define NXELEM (2 * NSTR * DIM)

__global__ void prep_kernel(const float* __restrict__ s, const float* __restrict__ q,
                            const float* __restrict__ w2, const float* __restrict__ b2,
                            const float* __restrict__ w3, const float* __restrict__ b3,
                            const float* __restrict__ w4, const float* __restrict__ b4,
                            const float* __restrict__ w5, const float* __restrict__ b5) {
    int idx = blockIdx.x * blockDim.x + threadIdx.x;
    if (idx < NCC) {
        int conv = idx / 150, c = idx - conv * 150;
        const float* bp = (conv == 0) ? b2 : (conv == 1) ? b3 : (conv == 2) ? b4 : b5;
        g_bias[idx] = bp[c];
    }
    if (idx < NWELEM) {
        int h = idx / (MSTR * DIM);
        int rem = idx - h * (MSTR * DIM);
        int m = rem / DIM;
        int d = rem - m * DIM;
        float v = 0.f;
        if (m < MTOT) {
            int conv = (m < 300) ? 0 : (m < 750) ? 1 : (m < 1350) ? 2 : 3;
            int base = (conv == 0) ? 0 : (conv == 1) ? 300 : (conv == 2) ? 750 : 1350;
            int k = conv + 2;
            int mm = m - base;
            int t = mm / 150, c = mm - t * 150;
            const float* w = (conv == 0) ? w2 : (conv == 1) ? w3 : (conv == 2) ? w4 : w5;
            v = w[(c * 1024 + h * DIM + d) * k + t];
        }
        g_Wh[idx] = __float2half(v);
    }
    if (idx < NXELEM) {
        int h = idx / (NSTR * DIM);
        int rem = idx - h * (NSTR * DIM);
        int n = rem / DIM;
        int d = rem - n * DIM;
        int r = n >> 5, l = n & 31;
        const float* x = (h ? q : s);
        float v = (l < LSEQ) ? x[((size_t)r * LSEQ + l) * DIM + d] : 0.f;
        g_Xh[idx] = __float2half(v);
    }
}

// ---------------------------------------------------------------------------
// gemm: 128x128 block tile, 4 warps (2x2, warp tile 64x64), BK=64,
// double-buffered cp.async, SW128 smem rows (128B), 64KB smem -> 2 CTAs/SM.
// ---------------------------------------------------------------------------
#define SM_BUF 32768
#define SM_TOTAL 65536

__global__ void __launch_bounds__(128, 2) gemm_kernel() {
    extern __shared__ char smem[];
    uint32_t sb = s2u(smem);
    int tid = threadIdx.x, wid = tid >> 5, lane = tid & 31;
    int bx = blockIdx.x, by = blockIdx.y, h = blockIdx.z;

    const __half* Wh = g_Wh + ((size_t)h * MSTR + by * 128) * DIM;
    const __half* Xh = g_Xh + ((size_t)h * NSTR + bx * 128) * DIM;
    const __half* mats[2] = {Wh, Xh};

    int wm0 = (wid >> 1) * 64;
    int wn0 = (wid & 1) * 64;

    float acc[4][8][4];
#pragma unroll
    for (int mt = 0; mt < 4; mt++)
#pragma unroll
        for (int nt = 0; nt < 8; nt++)
#pragma unroll
            for (int i = 0; i < 4; i++) acc[mt][nt][i] = 0.f;

#define STAGE(cc)                                                              \
    {                                                                          \
        int koff = (cc) * 64;                                                  \
        uint32_t bb = sb + ((cc) & 1) * SM_BUF;                                \
        _Pragma("unroll")                                                      \
        for (int rep = 0; rep < 16; rep++) {                                   \
            int cid = rep * 128 + tid;                                         \
            int mat = cid >> 10;                                               \
            int r = (cid >> 3) & 127;                                          \
            int kc = cid & 7;                                                  \
            cp16(bb + mat * 16384 + SW128(r * 128 + kc * 16),                  \
                 mats[mat] + (size_t)r * DIM + koff + kc * 8);                 \
        }                                                                      \
        asm volatile("cp.async.commit_group;");                                \
    }

    STAGE(0);
    for (int c = 0; c < NCH; c++) {
        if (c + 1 < NCH) {
            STAGE(c + 1);
            asm volatile("cp.async.wait_group 1;");
        } else {
            asm volatile("cp.async.wait_group 0;");
        }
        __syncthreads();

        uint32_t sbAh = sb + (c & 1) * SM_BUF;
        uint32_t sbBh = sbAh + 16384;
#pragma unroll
        for (int ks = 0; ks < 4; ks++) {
            uint32_t ah[4][4], bh[4][4];
#pragma unroll
            for (int mt = 0; mt < 4; mt++) {
                int row = wm0 + mt * 16 + (lane & 15);
                int colh = lane >> 4;
                uint32_t off = SW128(row * 128 + (ks * 2 + colh) * 16);
                ldsm4(ah[mt], sbAh + off);
            }
#pragma unroll
            for (int bt = 0; bt < 4; bt++) {
                int n = wn0 + bt * 16 + ((lane >> 4) << 3) + (lane & 7);
                int khalf = (lane >> 3) & 1;
                uint32_t off = SW128(n * 128 + ks * 32 + khalf * 16);
                ldsm4(bh[bt], sbBh + off);
            }
#pragma unroll
            for (int mt = 0; mt < 4; mt++)
#pragma unroll
                for (int nt = 0; nt < 8; nt++)
                    mma_f16(acc[mt][nt], ah[mt], bh[nt >> 1] + (nt & 1) * 2);
        }
        __syncthreads();
    }
#undef STAGE

    int gr = lane >> 2, gc = (lane & 3) * 2;
    float* Zp = g_Z + (size_t)h * MSTR * NSTR;
#pragma unroll
    for (int mt = 0; mt < 4; mt++) {
        int row0 = by * 128 + wm0 + mt * 16 + gr;
#pragma unroll
        for (int nt = 0; nt < 8; nt++) {
            int col = bx * 128 + wn0 + nt * 8 + gc;
            float2 lo = make_float2(acc[mt][nt][0], acc[mt][nt][1]);
            float2 hi = make_float2(acc[mt][nt][2], acc[mt][nt][3]);
            *(float2*)(Zp + (size_t)row0 * NSTR + col) = lo;
            *(float2*)(Zp + (size_t)(row0 + 8) * NSTR + col) = hi;
        }
    }
}

// ---------------------------------------------------------------------------
// epilogue: Y[h][r][conv*150+c][l] = sum_t Z[h][base+t*150+c][r*32 + l+t-pad]
// 2-row ILP per thread (c and c+75).
// ---------------------------------------------------------------------------
template <int CONV>
__device__ __forceinline__ void epi_body(int r, int h) {
    const int k = CONV + 2;
    const int pad = (CONV >= 2) ? 2 : 1;
    const int base = (CONV == 0) ? 0 : (CONV == 1) ? 300 : (CONV == 2) ? 750 : 1350;
    const float* Zp = g_Z + (size_t)h * MSTR * NSTR + r * 32;
    float* out = (h ? g_B : g_A) + (size_t)r * NCC * LP + CONV * 150 * LP;
    for (int i = threadIdx.x; i < 75 * 32; i += 256) {
        int c = i >> 5, l = i & 31;
        float v0 = -1e30f, v1 = -1e30f;
        if (l < LSEQ) {
            v0 = 0.f; v1 = 0.f;
#pragma unroll
            for (int t = 0; t < k; t++) {
                int lp = l + t - pad;
                if (lp >= 0 && lp < 32) {
                    v0 += __ldg(Zp + (size_t)(base + t * 150 + c) * NSTR + lp);
                    v1 += __ldg(Zp + (size_t)(base + t * 150 + c + 75) * NSTR + lp);
                }
            }
        }
        out[c * LP + l] = v0;
        out[(c + 75) * LP + l] = v1;
    }
}

__global__ void epilogue_kernel() {
    int r = blockIdx.x, h = blockIdx.z;
    switch (blockIdx.y) {
        case 0: epi_body<0>(r, h); break;
        case 1: epi_body<1>(r, h); break;
        case 2: epi_body<2>(r, h); break;
        case 3: epi_body<3>(r, h); break;
    }
}

// ---------------------------------------------------------------------------
// combine: register-tiled pair combine. Block = (pair-tile, cc-slab of 50).
// Thread owns (cci, ii) and accumulates m[5] over jj: per l4 step 1 sA read +
// 5 sB reads (broadcast across same-cci threads) -> 154B LDS per output.
// out_ch = max(0, max_l(A+B) + bias).
// ---------------------------------------------------------------------------
#define CSLAB 50
#define NSLAB (NCC / CSLAB)              // 12
#define CROWPAD 36                       // 16B-aligned, conflict-free phases
#define CROWSZ (CSLAB * CROWPAD)         // 1800 floats per staged row
#define CMB_SMEM (2 * 5 * CROWSZ * 4)    // 72000 bytes

__global__ void __launch_bounds__(256) combine_kernel(float* __restrict__ out) {
    extern __shared__ float cs[];
    float* sA = cs;                      // [5][CROWSZ]
    float* sB = cs + 5 * CROWSZ;

    int blk = blockIdx.x;                // 0..99 pair tile
    int sl = blockIdx.y;                 // 0..11 cc slab
    int b = blk / 25;
    int rem = blk - b * 25;
    int ig = rem / 5, jg = rem - (rem / 5) * 5;
    int b25 = b * 25;
    int tid = threadIdx.x;

    // stage 5 A rows + 5 B rows for this slab (float4 both sides)
    for (int idx = tid; idx < 10 * CSLAB * 8; idx += 256) {
        int row = idx / (CSLAB * 8);     // 0..9 (0-4: A, 5-9: B)
        int rest = idx - row * (CSLAB * 8);
        int cc = rest >> 3, l4 = rest & 7;
        int isB = row >= 5;
        int rloc = isB ? row - 5 : row;
        const float* gsrc = isB ? g_B : g_A;
        int grow = b25 + (isB ? jg : ig) * 5 + rloc;
        float4 v = *(const float4*)(gsrc + ((size_t)grow * NCC + sl * CSLAB + cc) * LP
                                    + l4 * 4);
        float* d = (isB ? sB : sA) + rloc * CROWSZ + cc * CROWPAD + l4 * 4;
        *(float4*)d = v;
    }
    __syncthreads();

    // thread = (ii, cci): ii = tid/50, cci = tid%50; 250 active threads
    if (tid < 250) {
        int ii = tid / CSLAB;
        int cci = tid - ii * CSLAB;
        const float4* ar = (const float4*)(sA + ii * CROWSZ + cci * CROWPAD);
        float m[5];
#pragma unroll
        for (int jj = 0; jj < 5; jj++) m[jj] = -3.0e38f;
#pragma unroll
        for (int l4 = 0; l4 < 8; l4++) {
            float4 a = ar[l4];
#pragma unroll
            for (int jj = 0; jj < 5; jj++) {
                float4 bb = *(const float4*)(sB + jj * CROWSZ + cci * CROWPAD
                                             + l4 * 4);
                float mm = fmaxf(fmaxf(a.x + bb.x, a.y + bb.y),
                                 fmaxf(a.z + bb.z, a.w + bb.w));
                m[jj] = fmaxf(m[jj], mm);
            }
        }
        int cc = sl * CSLAB + cci;
        float bias = g_bias[cc];
        int conv = cc / 150;
        int c = cc - conv * 150;
        int base_off = (c < 75) ? (conv * 75 + c) : (750000 + conv * 75 + (c - 75));
        int prow = b * 625 + (ig * 5 + ii) * 25 + jg * 5;
#pragma unroll
        for (int jj = 0; jj < 5; jj++) {
            float v = fmaxf(0.f, m[jj] + bias);
            out[(prow + jj) * 300 + base_off - ((c < 75) ? 0 : 750000)
                + ((c < 75) ? 0 : 750000)] = v;
        }
    }
}

// ---------------------------------------------------------------------------
extern "C" void kernel_launch(void* const* d_in, const int* in_sizes, int n_in,
                              void* d_out, int out_size) {
    const float* s  = (const float*)d_in[0];
    const float* q  = (const float*)d_in[1];
    const float* w2 = (const float*)d_in[2];
    const float* b2 = (const float*)d_in[3];
    const float* w3 = (const float*)d_in[4];
    const float* b3 = (const float*)d_in[5];
    const float* w4 = (const float*)d_in[6];
    const float* b4 = (const float*)d_in[7];
    const float* w5 = (const float*)d_in[8];
    const float* b5 = (const float*)d_in[9];
    float* out = (float*)d_out;

    cudaFuncSetAttribute(gemm_kernel, cudaFuncAttributeMaxDynamicSharedMemorySize,
                         SM_TOTAL);
    cudaFuncSetAttribute(combine_kernel, cudaFuncAttributeMaxDynamicSharedMemorySize,
                         CMB_SMEM);

    prep_kernel<<<(NXELEM + 255) / 256, 256>>>(s, q, w2, b2, w3, b3, w4, b4, w5, b5);
    gemm_kernel<<<dim3(NSTR / 128, MSTR / 128, 2), 128, SM_TOTAL>>>();
    epilogue_kernel<<<dim3(NROWS, 4, 2), 256>>>();
    combine_kernel<<<dim3(100, NSLAB), 256, CMB_SMEM>>>(out);
}